// round 9
// baseline (speedup 1.0000x reference)
#include <cuda_runtime.h>
#include <cuda_bf16.h>
#include <cstdint>

#define MAX_N 100000
#define MAX_E 1600000

// ---------------- scratch (static __device__ arrays) ----------------------
__device__ float g_h1  [MAX_N * 64];
__device__ float g_als1[MAX_N * 4];
__device__ float g_ald1[MAX_N * 4];
__device__ float g_out1[MAX_N * 64];
__device__ float g_h2  [MAX_N * 128];
__device__ float g_als2[MAX_N * 4];
__device__ float g_ald2[MAX_N * 4];
__device__ int   g_rowptr[MAX_N + 1];
__device__ int   g_cursor[MAX_N];
__device__ int   g_bsum[128];
__device__ int   g_ssrc[MAX_E];
// packed-bf16 mirrors of the gathered feature arrays (half gather traffic)
__device__ __nv_bfloat162 g_h1b[MAX_N * 32];
__device__ __nv_bfloat162 g_h2b[MAX_N * 64];

// ---------------- GEMM: C[M,NC] = A[M,K] @ W[K,NC] (+ bf16 mirror) --------
// tile 128 x NC, micro 8x8, 16*(NC/8) threads, reg-prefetch double buffer.
template<int K, int NC>
__global__ __launch_bounds__(16 * (NC / 8))
void gemm_kernel(const float* __restrict__ A, const float* __restrict__ W,
                 float* __restrict__ C, __nv_bfloat162* __restrict__ Cb, int M)
{
    constexpr int KC = 32;
    constexpr int TX = NC / 8;
    constexpr int T  = 16 * TX;
    constexpr int A_F4 = (128 * KC / 4) / T;
    constexpr int B_F4 = (KC * NC / 4) / T;

    __shared__ float As[128][33];
    __shared__ float Bs[KC][NC];

    const int tid = threadIdx.x;
    const int tx = tid % TX;
    const int ty = tid / TX;
    const int row0 = blockIdx.x * 128;

    float4 aPre[A_F4], bPre[B_F4];

    auto loadA = [&](int kk) {
#pragma unroll
        for (int t = 0; t < A_F4; t++) {
            int q = tid + t * T;
            int r = q >> 3, kc4 = q & 7;
            int gr = row0 + r;
            aPre[t] = (gr < M)
                ? *(const float4*)(A + (size_t)gr * K + kk + kc4 * 4)
                : make_float4(0.f, 0.f, 0.f, 0.f);
        }
    };
    auto loadB = [&](int kk) {
#pragma unroll
        for (int t = 0; t < B_F4; t++) {
            int q = tid + t * T;
            int r = q / (NC / 4), c4 = q % (NC / 4);
            bPre[t] = *(const float4*)(W + (size_t)(kk + r) * NC + c4 * 4);
        }
    };
    auto storeA = [&]() {
#pragma unroll
        for (int t = 0; t < A_F4; t++) {
            int q = tid + t * T;
            int r = q >> 3, kc4 = q & 7;
            As[r][kc4 * 4 + 0] = aPre[t].x;
            As[r][kc4 * 4 + 1] = aPre[t].y;
            As[r][kc4 * 4 + 2] = aPre[t].z;
            As[r][kc4 * 4 + 3] = aPre[t].w;
        }
    };
    auto storeB = [&]() {
#pragma unroll
        for (int t = 0; t < B_F4; t++) {
            int q = tid + t * T;
            int r = q / (NC / 4), c4 = q % (NC / 4);
            *(float4*)&Bs[r][c4 * 4] = bPre[t];
        }
    };

    float acc[8][8];
#pragma unroll
    for (int i = 0; i < 8; i++)
#pragma unroll
        for (int j = 0; j < 8; j++) acc[i][j] = 0.f;

    loadA(0); loadB(0);
    storeA(); storeB();
    __syncthreads();

    for (int kk = KC; kk <= K; kk += KC) {
        const bool more = (kk < K);
        if (more) { loadA(kk); loadB(kk); }

#pragma unroll
        for (int k = 0; k < KC; k++) {
            float a[8];
#pragma unroll
            for (int i = 0; i < 8; i++) a[i] = As[ty * 8 + i][k];
            float4 b0 = *(float4*)&Bs[k][tx * 8];
            float4 b1 = *(float4*)&Bs[k][tx * 8 + 4];
#pragma unroll
            for (int i = 0; i < 8; i++) {
                acc[i][0] = fmaf(a[i], b0.x, acc[i][0]);
                acc[i][1] = fmaf(a[i], b0.y, acc[i][1]);
                acc[i][2] = fmaf(a[i], b0.z, acc[i][2]);
                acc[i][3] = fmaf(a[i], b0.w, acc[i][3]);
                acc[i][4] = fmaf(a[i], b1.x, acc[i][4]);
                acc[i][5] = fmaf(a[i], b1.y, acc[i][5]);
                acc[i][6] = fmaf(a[i], b1.z, acc[i][6]);
                acc[i][7] = fmaf(a[i], b1.w, acc[i][7]);
            }
        }
        __syncthreads();
        if (more) {
            storeA(); storeB();
            __syncthreads();
        }
    }

#pragma unroll
    for (int i = 0; i < 8; i++) {
        int gr = row0 + ty * 8 + i;
        if (gr < M) {
            *(float4*)(C + (size_t)gr * NC + tx * 8) =
                make_float4(acc[i][0], acc[i][1], acc[i][2], acc[i][3]);
            *(float4*)(C + (size_t)gr * NC + tx * 8 + 4) =
                make_float4(acc[i][4], acc[i][5], acc[i][6], acc[i][7]);
            // bf16 mirror: 8 floats -> 4 bf162 -> one 16B store
            __nv_bfloat162 p0 = __floats2bfloat162_rn(acc[i][0], acc[i][1]);
            __nv_bfloat162 p1 = __floats2bfloat162_rn(acc[i][2], acc[i][3]);
            __nv_bfloat162 p2 = __floats2bfloat162_rn(acc[i][4], acc[i][5]);
            __nv_bfloat162 p3 = __floats2bfloat162_rn(acc[i][6], acc[i][7]);
            uint4 pk;
            pk.x = *(uint32_t*)&p0; pk.y = *(uint32_t*)&p1;
            pk.z = *(uint32_t*)&p2; pk.w = *(uint32_t*)&p3;
            *(uint4*)(Cb + (size_t)gr * (NC / 2) + tx * 4) = pk;
        }
    }
}

// ---------------- attention logits ----------------------------------------
template<int C>
__global__ void al_kernel(const float* __restrict__ h,
                          const float* __restrict__ a_src,
                          const float* __restrict__ a_dst,
                          float* __restrict__ als, float* __restrict__ ald, int n)
{
    int t = blockIdx.x * blockDim.x + threadIdx.x;
    if (t >= n * 4) return;
    int node = t >> 2, head = t & 3;
    const float* hp  = h + (size_t)node * (4 * C) + head * C;
    const float* asp = a_src + head * C;
    const float* adp = a_dst + head * C;
    float s1 = 0.f, s2 = 0.f;
#pragma unroll
    for (int c = 0; c < C; c += 4) {
        float4 hv = *(const float4*)(hp + c);
        float4 av = *(const float4*)(asp + c);
        float4 dv = *(const float4*)(adp + c);
        s1 += hv.x * av.x + hv.y * av.y + hv.z * av.z + hv.w * av.w;
        s2 += hv.x * dv.x + hv.y * dv.y + hv.z * dv.z + hv.w * dv.w;
    }
    als[t] = s1;
    ald[t] = s2;
}

// ---------------- CSR build ------------------------------------------------
__global__ void hist_kernel(const int* __restrict__ de, int E, int* __restrict__ cnt)
{
    int e = blockIdx.x * blockDim.x + threadIdx.x;
    if (e < E) atomicAdd(&cnt[de[e]], 1);
}

__global__ void scan_k1(int* __restrict__ data, int n, int* __restrict__ bsum)
{
    __shared__ int sh[256];
    int base = blockIdx.x * 2048 + threadIdx.x * 8;
    int v[8];
    int run = 0;
#pragma unroll
    for (int k = 0; k < 8; k++) {
        int t = (base + k < n) ? data[base + k] : 0;
        v[k] = run;
        run += t;
    }
    sh[threadIdx.x] = run;
    __syncthreads();
    for (int off = 1; off < 256; off <<= 1) {
        int t = (threadIdx.x >= off) ? sh[threadIdx.x - off] : 0;
        __syncthreads();
        sh[threadIdx.x] += t;
        __syncthreads();
    }
    int excl = sh[threadIdx.x] - run;
#pragma unroll
    for (int k = 0; k < 8; k++)
        if (base + k < n) data[base + k] = v[k] + excl;
    if (threadIdx.x == 255) bsum[blockIdx.x] = sh[255];
}

__global__ void scan_k2(int* __restrict__ bsum, int nb)
{
    if (threadIdx.x == 0) {
        int run = 0;
        for (int i = 0; i < nb; i++) { int t = bsum[i]; bsum[i] = run; run += t; }
    }
}

__global__ void scan_k3(int* __restrict__ data, int n, const int* __restrict__ bsum,
                        int* __restrict__ cursor, int E)
{
    int i = blockIdx.x * blockDim.x + threadIdx.x;
    if (i < n) {
        int v = data[i] + bsum[i >> 11];
        data[i] = v;
        cursor[i] = v;
    }
    if (i == 0) data[n] = E;
}

__global__ void scatter_kernel(const int* __restrict__ se, const int* __restrict__ de,
                               int E, int* __restrict__ cursor, int* __restrict__ ssrc)
{
    int e = blockIdx.x * blockDim.x + threadIdx.x;
    if (e < E) {
        int pos = atomicAdd(&cursor[de[e]], 1);
        ssrc[pos] = se[e];
    }
}

// ---------------- fused softmax-aggregate, CSR (layer 1) -------------------
// half-warp (16 lanes) per dst node; gathers the bf16 mirror.
__global__ void agg1_kernel(const int* __restrict__ rowptr,
                            const int* __restrict__ ssrc,
                            const float* __restrict__ als,
                            const float* __restrict__ ald,
                            const __nv_bfloat162* __restrict__ hb,
                            const float* __restrict__ bias,
                            float* __restrict__ out, int n)
{
    int gt   = blockIdx.x * blockDim.x + threadIdx.x;
    int node = gt >> 4;
    int li   = gt & 15;
    if (node >= n) return;
    int head = li >> 2;

    float aldv = ald[(size_t)node * 4 + head];

    float e0 = als[(size_t)node * 4 + head] + aldv;
    e0 = e0 > 0.f ? e0 : 0.2f * e0;
    float ex = __expf(e0);
    float den = ex;
    uint2 raw = *(const uint2*)(hb + (size_t)node * 32 + li * 2);
    float2 lo = __bfloat1622float2(*(__nv_bfloat162*)&raw.x);
    float2 hi = __bfloat1622float2(*(__nv_bfloat162*)&raw.y);
    float4 acc = make_float4(ex * lo.x, ex * lo.y, ex * hi.x, ex * hi.y);

    int j1 = rowptr[node + 1];
    for (int j = rowptr[node]; j < j1; j++) {
        int s = ssrc[j];
        float e = als[(size_t)s * 4 + head] + aldv;
        e = e > 0.f ? e : 0.2f * e;
        float w = __expf(e);
        den += w;
        uint2 r2 = *(const uint2*)(hb + (size_t)s * 32 + li * 2);
        float2 l2 = __bfloat1622float2(*(__nv_bfloat162*)&r2.x);
        float2 h2v = __bfloat1622float2(*(__nv_bfloat162*)&r2.y);
        acc.x = fmaf(w, l2.x, acc.x);
        acc.y = fmaf(w, l2.y, acc.y);
        acc.z = fmaf(w, h2v.x, acc.z);
        acc.w = fmaf(w, h2v.y, acc.w);
    }
    float inv = 1.f / den;
    float4 o;
    o.x = acc.x * inv + bias[li * 4 + 0];
    o.y = acc.y * inv + bias[li * 4 + 1];
    o.z = acc.z * inv + bias[li * 4 + 2];
    o.w = acc.w * inv + bias[li * 4 + 3];
    ((float4*)(out + (size_t)node * 64))[li] = o;
}

// ---------------- layer 2: aggregate + head-mean + bias + elu + logsoftmax -
// warp per node; gathers the bf16 mirror of h2.
__global__ void agg2_final_kernel(const int* __restrict__ rowptr,
                                  const int* __restrict__ ssrc,
                                  const float* __restrict__ als,
                                  const float* __restrict__ ald,
                                  const __nv_bfloat162* __restrict__ hb,
                                  const float* __restrict__ b2,
                                  float* __restrict__ y, int n)
{
    int lane = threadIdx.x & 31;
    int node = (blockIdx.x * blockDim.x + threadIdx.x) >> 5;
    if (node >= n) return;
    int head = lane >> 3;

    float aldv = ald[(size_t)node * 4 + head];

    float e0 = als[(size_t)node * 4 + head] + aldv;
    e0 = e0 > 0.f ? e0 : 0.2f * e0;
    float ex = __expf(e0);
    float den = ex;
    uint2 raw = *(const uint2*)(hb + (size_t)node * 64 + lane * 2);
    float2 lo = __bfloat1622float2(*(__nv_bfloat162*)&raw.x);
    float2 hi = __bfloat1622float2(*(__nv_bfloat162*)&raw.y);
    float4 acc = make_float4(ex * lo.x, ex * lo.y, ex * hi.x, ex * hi.y);

    int j1 = rowptr[node + 1];
    for (int j = rowptr[node]; j < j1; j++) {
        int s = ssrc[j];
        float e = als[(size_t)s * 4 + head] + aldv;
        e = e > 0.f ? e : 0.2f * e;
        float w = __expf(e);
        den += w;
        uint2 r2 = *(const uint2*)(hb + (size_t)s * 64 + lane * 2);
        float2 l2 = __bfloat1622float2(*(__nv_bfloat162*)&r2.x);
        float2 h2v = __bfloat1622float2(*(__nv_bfloat162*)&r2.y);
        acc.x = fmaf(w, l2.x, acc.x);
        acc.y = fmaf(w, l2.y, acc.y);
        acc.z = fmaf(w, h2v.x, acc.z);
        acc.w = fmaf(w, h2v.y, acc.w);
    }
    float inv = 1.f / den;
    float4 v = make_float4(acc.x * inv, acc.y * inv, acc.z * inv, acc.w * inv);

    v.x += __shfl_xor_sync(0xffffffffu, v.x, 8);
    v.y += __shfl_xor_sync(0xffffffffu, v.y, 8);
    v.z += __shfl_xor_sync(0xffffffffu, v.z, 8);
    v.w += __shfl_xor_sync(0xffffffffu, v.w, 8);
    v.x += __shfl_xor_sync(0xffffffffu, v.x, 16);
    v.y += __shfl_xor_sync(0xffffffffu, v.y, 16);
    v.z += __shfl_xor_sync(0xffffffffu, v.z, 16);
    v.w += __shfl_xor_sync(0xffffffffu, v.w, 16);
    int c0 = (lane & 7) * 4;
    v.x = 0.25f * v.x + b2[c0 + 0];
    v.y = 0.25f * v.y + b2[c0 + 1];
    v.z = 0.25f * v.z + b2[c0 + 2];
    v.w = 0.25f * v.w + b2[c0 + 3];
    v.x = v.x > 0.f ? v.x : expm1f(v.x);
    v.y = v.y > 0.f ? v.y : expm1f(v.y);
    v.z = v.z > 0.f ? v.z : expm1f(v.z);
    v.w = v.w > 0.f ? v.w : expm1f(v.w);
    float m = fmaxf(fmaxf(v.x, v.y), fmaxf(v.z, v.w));
#pragma unroll
    for (int off = 1; off < 8; off <<= 1)
        m = fmaxf(m, __shfl_xor_sync(0xffffffffu, m, off));
    float s = expf(v.x - m) + expf(v.y - m) + expf(v.z - m) + expf(v.w - m);
#pragma unroll
    for (int off = 1; off < 8; off <<= 1)
        s += __shfl_xor_sync(0xffffffffu, s, off);
    float ls = m + logf(s);
    if (lane < 8) {
        float4 o = make_float4(v.x - ls, v.y - ls, v.z - ls, v.w - ls);
        ((float4*)(y + (size_t)node * 32))[lane] = o;
    }
}

// ---------------------------------------------------------------------------
extern "C" void kernel_launch(void* const* d_in, const int* in_sizes, int n_in,
                              void* d_out, int out_size)
{
    const float* x   = (const float*)d_in[0];
    const int*   ei  = (const int*)d_in[1];
    const float* W1  = (const float*)d_in[2];
    const float* as1 = (const float*)d_in[3];
    const float* ad1 = (const float*)d_in[4];
    const float* b1  = (const float*)d_in[5];
    const float* W2  = (const float*)d_in[6];
    const float* as2 = (const float*)d_in[7];
    const float* ad2 = (const float*)d_in[8];
    const float* b2  = (const float*)d_in[9];
    float*       y   = (float*)d_out;

    const int n = in_sizes[0] / 128;
    const int E = in_sizes[1] / 2;
    const int* se = ei;
    const int* de = ei + E;

    float *h1, *als1, *ald1, *out1, *h2, *als2, *ald2;
    int *rowptr, *cursor, *bsum, *ssrc;
    __nv_bfloat162 *h1b, *h2b;
    cudaGetSymbolAddress((void**)&h1,     g_h1);
    cudaGetSymbolAddress((void**)&als1,   g_als1);
    cudaGetSymbolAddress((void**)&ald1,   g_ald1);
    cudaGetSymbolAddress((void**)&out1,   g_out1);
    cudaGetSymbolAddress((void**)&h2,     g_h2);
    cudaGetSymbolAddress((void**)&als2,   g_als2);
    cudaGetSymbolAddress((void**)&ald2,   g_ald2);
    cudaGetSymbolAddress((void**)&rowptr, g_rowptr);
    cudaGetSymbolAddress((void**)&cursor, g_cursor);
    cudaGetSymbolAddress((void**)&bsum,   g_bsum);
    cudaGetSymbolAddress((void**)&ssrc,   g_ssrc);
    cudaGetSymbolAddress((void**)&h1b,    g_h1b);
    cudaGetSymbolAddress((void**)&h2b,    g_h2b);

    const int nb = (n + 2047) / 2048;

    // ---- CSR build (shared by both layers) ----
    cudaMemsetAsync(rowptr, 0, (size_t)n * sizeof(int));
    hist_kernel<<<(E + 255) / 256, 256>>>(de, E, rowptr);
    scan_k1<<<nb, 256>>>(rowptr, n, bsum);
    scan_k2<<<1, 32>>>(bsum, nb);
    scan_k3<<<(n + 255) / 256, 256>>>(rowptr, n, bsum, cursor, E);
    scatter_kernel<<<(E + 255) / 256, 256>>>(se, de, E, cursor, ssrc);

    // ---- layer 1 ----
    gemm_kernel<128, 64><<<(n + 127) / 128, 128>>>(x, W1, h1, h1b, n);
    al_kernel<16><<<(n * 4 + 255) / 256, 256>>>(h1, as1, ad1, als1, ald1, n);
    agg1_kernel<<<(int)(((long long)n * 16 + 255) / 256), 256>>>(
        rowptr, ssrc, als1, ald1, h1b, b1, out1, n);

    // ---- layer 2 ----
    gemm_kernel<64, 128><<<(n + 127) / 128, 256>>>(out1, W2, h2, h2b, n);
    al_kernel<32><<<(n * 4 + 255) / 256, 256>>>(h2, as2, ad2, als2, ald2, n);
    agg2_final_kernel<<<(int)(((long long)n * 32 + 255) / 256), 256>>>(
        rowptr, ssrc, als2, ald2, h2b, b2, y, n);
}

// round 10
// speedup vs baseline: 1.2023x; 1.2023x over previous
#include <cuda_runtime.h>

#define MAX_N 100000
#define MAX_E 1600000

// ---------------- scratch (static __device__ arrays) ----------------------
__device__ float g_h1  [MAX_N * 64];
__device__ float g_als1[MAX_N * 4];
__device__ float g_ald1[MAX_N * 4];
__device__ float g_out1[MAX_N * 64];
__device__ float g_h2  [MAX_N * 128];
__device__ float g_als2[MAX_N * 4];
__device__ float g_ald2[MAX_N * 4];
__device__ int   g_rowptr[MAX_N + 1];
__device__ int   g_cursor[MAX_N];
__device__ int   g_bsum[128];
__device__ int   g_ssrc[MAX_E];

// ---------------- GEMM + fused attention logits ---------------------------
// C[M,NC] = (A[M,K] (+abias)) @ W[K,NC]; tile 128x64 (blockIdx.y splits NC),
// micro 8x4, 256 threads. Epilogue computes als/ald = C-row . a_{src,dst}
// per head via per-thread partial dots + tx-group shuffles.
template<int K, int NC, bool ADD_BIAS>
__global__ __launch_bounds__(256)
void gemm_kernel(const float* __restrict__ A, const float* __restrict__ W,
                 const float* __restrict__ abias,
                 const float* __restrict__ a_src, const float* __restrict__ a_dst,
                 float* __restrict__ C,
                 float* __restrict__ als, float* __restrict__ ald, int M)
{
    constexpr int KC = 32;
    __shared__ float As[128][KC + 4];
    __shared__ float Bs[KC][64];

    const int tx = threadIdx.x & 15;
    const int ty = threadIdx.x >> 4;
    const int row0 = blockIdx.x * 128;
    const int col0 = blockIdx.y * 64;

    float acc[8][4];
#pragma unroll
    for (int i = 0; i < 8; i++)
#pragma unroll
        for (int j = 0; j < 4; j++) acc[i][j] = 0.f;

    for (int kk = 0; kk < K; kk += KC) {
#pragma unroll
        for (int i = 0; i < 4; i++) {
            int idx = threadIdx.x + i * 256;
            int r = idx >> 3, c4 = idx & 7;
            float4 v = make_float4(0.f, 0.f, 0.f, 0.f);
            int gr = row0 + r;
            if (gr < M)
                v = *(const float4*)(A + (size_t)gr * K + kk + c4 * 4);
            if (ADD_BIAS) {
                v.x += abias[kk + c4 * 4 + 0];
                v.y += abias[kk + c4 * 4 + 1];
                v.z += abias[kk + c4 * 4 + 2];
                v.w += abias[kk + c4 * 4 + 3];
            }
            *(float4*)&As[r][c4 * 4] = v;
        }
#pragma unroll
        for (int i = 0; i < 2; i++) {
            int idx = threadIdx.x + i * 256;
            int r = idx >> 4, c4 = idx & 15;
            *(float4*)&Bs[r][c4 * 4] =
                *(const float4*)(W + (size_t)(kk + r) * NC + col0 + c4 * 4);
        }
        __syncthreads();

#pragma unroll
        for (int k = 0; k < KC; k++) {
            float4 b = *(float4*)&Bs[k][tx * 4];
#pragma unroll
            for (int i = 0; i < 8; i++) {
                float a = As[ty * 8 + i][k];
                acc[i][0] += a * b.x;
                acc[i][1] += a * b.y;
                acc[i][2] += a * b.z;
                acc[i][3] += a * b.w;
            }
        }
        __syncthreads();
    }

    // ---- store C ----
#pragma unroll
    for (int i = 0; i < 8; i++) {
        int gr = row0 + ty * 8 + i;
        if (gr < M)
            *(float4*)(C + (size_t)gr * NC + col0 + tx * 4) =
                make_float4(acc[i][0], acc[i][1], acc[i][2], acc[i][3]);
    }

    // ---- fused logits: als/ald[row][head] = C[row, head-cols] . a[head] ----
    constexpr int CPH = NC / 4;          // cols per head (16 or 32)
    constexpr int G   = CPH / 4;         // tx lanes per head (4 or 8)
    const int gcol0 = col0 + tx * 4;
    const int head = gcol0 / CPH;
    float asv[4], adv[4];
#pragma unroll
    for (int j = 0; j < 4; j++) {
        asv[j] = a_src[gcol0 + j];       // a_* is [4][CPH] contiguous = NC floats
        adv[j] = a_dst[gcol0 + j];
    }
#pragma unroll
    for (int i = 0; i < 8; i++) {
        float s1 = acc[i][0] * asv[0] + acc[i][1] * asv[1]
                 + acc[i][2] * asv[2] + acc[i][3] * asv[3];
        float s2 = acc[i][0] * adv[0] + acc[i][1] * adv[1]
                 + acc[i][2] * adv[2] + acc[i][3] * adv[3];
#pragma unroll
        for (int off = 1; off < G; off <<= 1) {
            s1 += __shfl_xor_sync(0xffffffffu, s1, off);
            s2 += __shfl_xor_sync(0xffffffffu, s2, off);
        }
        int gr = row0 + ty * 8 + i;
        if ((tx & (G - 1)) == 0 && gr < M) {
            als[(size_t)gr * 4 + head] = s1;
            ald[(size_t)gr * 4 + head] = s2;
        }
    }
}

// ---------------- CSR build ------------------------------------------------
__global__ void hist_kernel(const int* __restrict__ de, int E, int* __restrict__ cnt)
{
    int e = blockIdx.x * blockDim.x + threadIdx.x;
    if (e < E) atomicAdd(&cnt[de[e]], 1);
}

__global__ void scan_k1(int* __restrict__ data, int n, int* __restrict__ bsum)
{
    __shared__ int sh[256];
    int base = blockIdx.x * 2048 + threadIdx.x * 8;
    int v[8];
    int run = 0;
#pragma unroll
    for (int k = 0; k < 8; k++) {
        int t = (base + k < n) ? data[base + k] : 0;
        v[k] = run;
        run += t;
    }
    sh[threadIdx.x] = run;
    __syncthreads();
    for (int off = 1; off < 256; off <<= 1) {
        int t = (threadIdx.x >= off) ? sh[threadIdx.x - off] : 0;
        __syncthreads();
        sh[threadIdx.x] += t;
        __syncthreads();
    }
    int excl = sh[threadIdx.x] - run;
#pragma unroll
    for (int k = 0; k < 8; k++)
        if (base + k < n) data[base + k] = v[k] + excl;
    if (threadIdx.x == 255) bsum[blockIdx.x] = sh[255];
}

// scan_k3 with the (tiny) cross-block scan of bsum folded in: every thread
// block spans indices within ONE 2048-chunk, so thread 0 computes the chunk
// prefix serially (<= 49 adds) and broadcasts via shared.
__global__ void scan_k3m(int* __restrict__ data, int n, const int* __restrict__ bsum,
                         int* __restrict__ cursor, int E)
{
    __shared__ int spre;
    if (threadIdx.x == 0) {
        int blk = (blockIdx.x * 256) >> 11;
        int p = 0;
        for (int b = 0; b < blk; b++) p += bsum[b];
        spre = p;
    }
    __syncthreads();
    int i = blockIdx.x * blockDim.x + threadIdx.x;
    if (i < n) {
        int v = data[i] + spre;
        data[i] = v;
        cursor[i] = v;
    }
    if (i == 0) data[n] = E;
}

__global__ void scatter_kernel(const int* __restrict__ se, const int* __restrict__ de,
                               int E, int* __restrict__ cursor, int* __restrict__ ssrc)
{
    int e = blockIdx.x * blockDim.x + threadIdx.x;
    if (e < E) {
        int pos = atomicAdd(&cursor[de[e]], 1);
        ssrc[pos] = se[e];
    }
}

// ---------------- fused softmax-aggregate, CSR (layer 1) -------------------
template<int C>
__global__ void agg_csr_kernel(const int* __restrict__ rowptr,
                               const int* __restrict__ ssrc,
                               const float* __restrict__ als,
                               const float* __restrict__ ald,
                               const float* __restrict__ h,
                               const float* __restrict__ bias,
                               float* __restrict__ out, int n)
{
    constexpr int HC = 4 * C;
    constexpr int G  = HC / 4;
    int gt   = blockIdx.x * blockDim.x + threadIdx.x;
    int node = gt / G;
    int li   = gt % G;
    if (node >= n) return;
    int head = li / (C / 4);

    float aldv = ald[(size_t)node * 4 + head];

    float e0 = als[(size_t)node * 4 + head] + aldv;
    e0 = e0 > 0.f ? e0 : 0.2f * e0;
    float ex = __expf(e0);
    float den = ex;
    float4 hv = ((const float4*)(h + (size_t)node * HC))[li];
    float4 acc = make_float4(ex * hv.x, ex * hv.y, ex * hv.z, ex * hv.w);

    int j1 = rowptr[node + 1];
    for (int j = rowptr[node]; j < j1; j++) {
        int s = ssrc[j];
        float e = als[(size_t)s * 4 + head] + aldv;
        e = e > 0.f ? e : 0.2f * e;
        float w = __expf(e);
        den += w;
        float4 v = ((const float4*)(h + (size_t)s * HC))[li];
        acc.x = fmaf(w, v.x, acc.x);
        acc.y = fmaf(w, v.y, acc.y);
        acc.z = fmaf(w, v.z, acc.z);
        acc.w = fmaf(w, v.w, acc.w);
    }
    float inv = 1.f / den;
    float4 o;
    o.x = acc.x * inv + bias[li * 4 + 0];
    o.y = acc.y * inv + bias[li * 4 + 1];
    o.z = acc.z * inv + bias[li * 4 + 2];
    o.w = acc.w * inv + bias[li * 4 + 3];
    ((float4*)(out + (size_t)node * HC))[li] = o;
}

// ---------------- layer 2: aggregate + head-mean + bias + elu + logsoftmax -
__global__ void agg2_final_kernel(const int* __restrict__ rowptr,
                                  const int* __restrict__ ssrc,
                                  const float* __restrict__ als,
                                  const float* __restrict__ ald,
                                  const float* __restrict__ h,
                                  const float* __restrict__ b2,
                                  float* __restrict__ y, int n)
{
    int lane = threadIdx.x & 31;
    int node = (blockIdx.x * blockDim.x + threadIdx.x) >> 5;
    if (node >= n) return;
    int head = lane >> 3;

    float aldv = ald[(size_t)node * 4 + head];

    float e0 = als[(size_t)node * 4 + head] + aldv;
    e0 = e0 > 0.f ? e0 : 0.2f * e0;
    float ex = __expf(e0);
    float den = ex;
    float4 hv = ((const float4*)(h + (size_t)node * 128))[lane];
    float4 acc = make_float4(ex * hv.x, ex * hv.y, ex * hv.z, ex * hv.w);

    int j1 = rowptr[node + 1];
    for (int j = rowptr[node]; j < j1; j++) {
        int s = ssrc[j];
        float e = als[(size_t)s * 4 + head] + aldv;
        e = e > 0.f ? e : 0.2f * e;
        float w = __expf(e);
        den += w;
        float4 v = ((const float4*)(h + (size_t)s * 128))[lane];
        acc.x = fmaf(w, v.x, acc.x);
        acc.y = fmaf(w, v.y, acc.y);
        acc.z = fmaf(w, v.z, acc.z);
        acc.w = fmaf(w, v.w, acc.w);
    }
    float inv = 1.f / den;
    float4 v = make_float4(acc.x * inv, acc.y * inv, acc.z * inv, acc.w * inv);

    v.x += __shfl_xor_sync(0xffffffffu, v.x, 8);
    v.y += __shfl_xor_sync(0xffffffffu, v.y, 8);
    v.z += __shfl_xor_sync(0xffffffffu, v.z, 8);
    v.w += __shfl_xor_sync(0xffffffffu, v.w, 8);
    v.x += __shfl_xor_sync(0xffffffffu, v.x, 16);
    v.y += __shfl_xor_sync(0xffffffffu, v.y, 16);
    v.z += __shfl_xor_sync(0xffffffffu, v.z, 16);
    v.w += __shfl_xor_sync(0xffffffffu, v.w, 16);
    int c0 = (lane & 7) * 4;
    v.x = 0.25f * v.x + b2[c0 + 0];
    v.y = 0.25f * v.y + b2[c0 + 1];
    v.z = 0.25f * v.z + b2[c0 + 2];
    v.w = 0.25f * v.w + b2[c0 + 3];
    v.x = v.x > 0.f ? v.x : expm1f(v.x);
    v.y = v.y > 0.f ? v.y : expm1f(v.y);
    v.z = v.z > 0.f ? v.z : expm1f(v.z);
    v.w = v.w > 0.f ? v.w : expm1f(v.w);
    float m = fmaxf(fmaxf(v.x, v.y), fmaxf(v.z, v.w));
#pragma unroll
    for (int off = 1; off < 8; off <<= 1)
        m = fmaxf(m, __shfl_xor_sync(0xffffffffu, m, off));
    float s = expf(v.x - m) + expf(v.y - m) + expf(v.z - m) + expf(v.w - m);
#pragma unroll
    for (int off = 1; off < 8; off <<= 1)
        s += __shfl_xor_sync(0xffffffffu, s, off);
    float ls = m + logf(s);
    if (lane < 8) {
        float4 o = make_float4(v.x - ls, v.y - ls, v.z - ls, v.w - ls);
        ((float4*)(y + (size_t)node * 32))[lane] = o;
    }
}

// ---------------------------------------------------------------------------
extern "C" void kernel_launch(void* const* d_in, const int* in_sizes, int n_in,
                              void* d_out, int out_size)
{
    const float* x   = (const float*)d_in[0];
    const int*   ei  = (const int*)d_in[1];
    const float* W1  = (const float*)d_in[2];
    const float* as1 = (const float*)d_in[3];
    const float* ad1 = (const float*)d_in[4];
    const float* b1  = (const float*)d_in[5];
    const float* W2  = (const float*)d_in[6];
    const float* as2 = (const float*)d_in[7];
    const float* ad2 = (const float*)d_in[8];
    const float* b2  = (const float*)d_in[9];
    float*       y   = (float*)d_out;

    const int n = in_sizes[0] / 128;
    const int E = in_sizes[1] / 2;
    const int* se = ei;
    const int* de = ei + E;

    float *h1, *als1, *ald1, *out1, *h2, *als2, *ald2;
    int *rowptr, *cursor, *bsum, *ssrc;
    cudaGetSymbolAddress((void**)&h1,     g_h1);
    cudaGetSymbolAddress((void**)&als1,   g_als1);
    cudaGetSymbolAddress((void**)&ald1,   g_ald1);
    cudaGetSymbolAddress((void**)&out1,   g_out1);
    cudaGetSymbolAddress((void**)&h2,     g_h2);
    cudaGetSymbolAddress((void**)&als2,   g_als2);
    cudaGetSymbolAddress((void**)&ald2,   g_ald2);
    cudaGetSymbolAddress((void**)&rowptr, g_rowptr);
    cudaGetSymbolAddress((void**)&cursor, g_cursor);
    cudaGetSymbolAddress((void**)&bsum,   g_bsum);
    cudaGetSymbolAddress((void**)&ssrc,   g_ssrc);

    const int nb = (n + 2047) / 2048;

    // ---- CSR build part 1 (kernels 1-3), then gemm1 as 4th (profiled) ----
    cudaMemsetAsync(rowptr, 0, (size_t)n * sizeof(int));
    hist_kernel<<<(E + 255) / 256, 256>>>(de, E, rowptr);                  // 1
    scan_k1<<<nb, 256>>>(rowptr, n, bsum);                                 // 2
    scan_k3m<<<(n + 255) / 256, 256>>>(rowptr, n, bsum, cursor, E);        // 3

    gemm_kernel<128, 64, false>                                            // 4
        <<<dim3((n + 127) / 128, 1), 256>>>(x, W1, nullptr, as1, ad1,
                                            h1, als1, ald1, n);

    scatter_kernel<<<(E + 255) / 256, 256>>>(se, de, E, cursor, ssrc);     // 5

    // ---- layer 1 aggregation (adds b1) ----
    agg_csr_kernel<16><<<(int)(((long long)n * 16 + 255) / 256), 256>>>(
        rowptr, ssrc, als1, ald1, h1, b1, out1, n);                        // 6

    // ---- layer 2 ----
    gemm_kernel<64, 128, true>                                             // 7
        <<<dim3((n + 127) / 128, 2), 256>>>(out1, W2, b1, as2, ad2,
                                            h2, als2, ald2, n);
    agg2_final_kernel<<<(int)(((long long)n * 32 + 255) / 256), 256>>>(
        rowptr, ssrc, als2, ald2, h2, b2, y, n);                           // 8
}

// round 11
// speedup vs baseline: 1.2045x; 1.0018x over previous
#include <cuda_runtime.h>

#define MAX_N 100000
#define MAX_E 1600000

// ---------------- scratch (static __device__ arrays) ----------------------
__device__ float g_h1  [MAX_N * 64];
__device__ float g_als1[MAX_N * 4];
__device__ float g_ald1[MAX_N * 4];
__device__ float g_out1[MAX_N * 64];
__device__ float g_h2  [MAX_N * 128];
__device__ float g_als2[MAX_N * 4];
__device__ float g_ald2[MAX_N * 4];
__device__ int   g_rowptr[MAX_N + 1];
__device__ int   g_cursor[MAX_N];
__device__ int   g_bsum[128];
__device__ int   g_ssrc[MAX_E];

// ---------------- GEMM + fused attention logits ---------------------------
// C[M,NC] = (A[M,K] (+abias)) @ W[K,NC]; tile 128x64 (blockIdx.y splits NC),
// micro 8x4, 256 threads. A smem tile stored TRANSPOSED (As[k][row], stride
// 132 floats) so each thread's 8 A-values per k load as 2x LDS.128 instead
// of 8x LDS.32. Epilogue computes als/ald per head via partial dots+shuffles.
template<int K, int NC, bool ADD_BIAS>
__global__ __launch_bounds__(256)
void gemm_kernel(const float* __restrict__ A, const float* __restrict__ W,
                 const float* __restrict__ abias,
                 const float* __restrict__ a_src, const float* __restrict__ a_dst,
                 float* __restrict__ C,
                 float* __restrict__ als, float* __restrict__ ald, int M)
{
    constexpr int KC = 32;
    __shared__ __align__(16) float As[KC][132];   // transposed, 16B-aligned rows
    __shared__ float Bs[KC][64];

    const int tx = threadIdx.x & 15;
    const int ty = threadIdx.x >> 4;
    const int row0 = blockIdx.x * 128;
    const int col0 = blockIdx.y * 64;

    float acc[8][4];
#pragma unroll
    for (int i = 0; i < 8; i++)
#pragma unroll
        for (int j = 0; j < 4; j++) acc[i][j] = 0.f;

    for (int kk = 0; kk < K; kk += KC) {
        // load A tile: 128 rows x 32 k = 1024 float4; scatter transposed
#pragma unroll
        for (int i = 0; i < 4; i++) {
            int idx = threadIdx.x + i * 256;
            int r = idx >> 3, c4 = idx & 7;
            float4 v = make_float4(0.f, 0.f, 0.f, 0.f);
            int gr = row0 + r;
            if (gr < M)
                v = *(const float4*)(A + (size_t)gr * K + kk + c4 * 4);
            if (ADD_BIAS) {
                v.x += abias[kk + c4 * 4 + 0];
                v.y += abias[kk + c4 * 4 + 1];
                v.z += abias[kk + c4 * 4 + 2];
                v.w += abias[kk + c4 * 4 + 3];
            }
            As[c4 * 4 + 0][r] = v.x;
            As[c4 * 4 + 1][r] = v.y;
            As[c4 * 4 + 2][r] = v.z;
            As[c4 * 4 + 3][r] = v.w;
        }
#pragma unroll
        for (int i = 0; i < 2; i++) {
            int idx = threadIdx.x + i * 256;
            int r = idx >> 4, c4 = idx & 15;
            *(float4*)&Bs[r][c4 * 4] =
                *(const float4*)(W + (size_t)(kk + r) * NC + col0 + c4 * 4);
        }
        __syncthreads();

#pragma unroll
        for (int k = 0; k < KC; k++) {
            float4 a0 = *(float4*)&As[k][ty * 8];
            float4 a1 = *(float4*)&As[k][ty * 8 + 4];
            float a[8] = {a0.x, a0.y, a0.z, a0.w, a1.x, a1.y, a1.z, a1.w};
            float4 b = *(float4*)&Bs[k][tx * 4];
#pragma unroll
            for (int i = 0; i < 8; i++) {
                acc[i][0] += a[i] * b.x;
                acc[i][1] += a[i] * b.y;
                acc[i][2] += a[i] * b.z;
                acc[i][3] += a[i] * b.w;
            }
        }
        __syncthreads();
    }

    // ---- store C ----
#pragma unroll
    for (int i = 0; i < 8; i++) {
        int gr = row0 + ty * 8 + i;
        if (gr < M)
            *(float4*)(C + (size_t)gr * NC + col0 + tx * 4) =
                make_float4(acc[i][0], acc[i][1], acc[i][2], acc[i][3]);
    }

    // ---- fused logits: als/ald[row][head] = C[row, head-cols] . a[head] ----
    constexpr int CPH = NC / 4;          // cols per head (16 or 32)
    constexpr int G   = CPH / 4;         // tx lanes per head (4 or 8)
    const int gcol0 = col0 + tx * 4;
    const int head = gcol0 / CPH;
    float asv[4], adv[4];
#pragma unroll
    for (int j = 0; j < 4; j++) {
        asv[j] = a_src[gcol0 + j];
        adv[j] = a_dst[gcol0 + j];
    }
#pragma unroll
    for (int i = 0; i < 8; i++) {
        float s1 = acc[i][0] * asv[0] + acc[i][1] * asv[1]
                 + acc[i][2] * asv[2] + acc[i][3] * asv[3];
        float s2 = acc[i][0] * adv[0] + acc[i][1] * adv[1]
                 + acc[i][2] * adv[2] + acc[i][3] * adv[3];
#pragma unroll
        for (int off = 1; off < G; off <<= 1) {
            s1 += __shfl_xor_sync(0xffffffffu, s1, off);
            s2 += __shfl_xor_sync(0xffffffffu, s2, off);
        }
        int gr = row0 + ty * 8 + i;
        if ((tx & (G - 1)) == 0 && gr < M) {
            als[(size_t)gr * 4 + head] = s1;
            ald[(size_t)gr * 4 + head] = s2;
        }
    }
}

// ---------------- CSR build ------------------------------------------------
__global__ void hist_kernel(const int* __restrict__ de, int E, int* __restrict__ cnt)
{
    int e = blockIdx.x * blockDim.x + threadIdx.x;
    if (e < E) atomicAdd(&cnt[de[e]], 1);
}

__global__ void scan_k1(int* __restrict__ data, int n, int* __restrict__ bsum)
{
    __shared__ int sh[256];
    int base = blockIdx.x * 2048 + threadIdx.x * 8;
    int v[8];
    int run = 0;
#pragma unroll
    for (int k = 0; k < 8; k++) {
        int t = (base + k < n) ? data[base + k] : 0;
        v[k] = run;
        run += t;
    }
    sh[threadIdx.x] = run;
    __syncthreads();
    for (int off = 1; off < 256; off <<= 1) {
        int t = (threadIdx.x >= off) ? sh[threadIdx.x - off] : 0;
        __syncthreads();
        sh[threadIdx.x] += t;
        __syncthreads();
    }
    int excl = sh[threadIdx.x] - run;
#pragma unroll
    for (int k = 0; k < 8; k++)
        if (base + k < n) data[base + k] = v[k] + excl;
    if (threadIdx.x == 255) bsum[blockIdx.x] = sh[255];
}

// scan_k3 with the cross-block scan of bsum folded in. bsum is first loaded
// into shared by 64 threads in parallel, then thread 0 does the short serial
// prefix over LDS hits (29 cyc) instead of dependent global loads.
__global__ void scan_k3m(int* __restrict__ data, int n, const int* __restrict__ bsum,
                         int* __restrict__ cursor, int E)
{
    __shared__ int sb[128];
    __shared__ int spre;
    int blk = (blockIdx.x * 256) >> 11;
    if (threadIdx.x < 128)
        sb[threadIdx.x] = (threadIdx.x < blk) ? bsum[threadIdx.x] : 0;
    __syncthreads();
    if (threadIdx.x == 0) {
        int p = 0;
        for (int b = 0; b < blk; b++) p += sb[b];
        spre = p;
    }
    __syncthreads();
    int i = blockIdx.x * blockDim.x + threadIdx.x;
    if (i < n) {
        int v = data[i] + spre;
        data[i] = v;
        cursor[i] = v;
    }
    if (i == 0) data[n] = E;
}

__global__ void scatter_kernel(const int* __restrict__ se, const int* __restrict__ de,
                               int E, int* __restrict__ cursor, int* __restrict__ ssrc)
{
    int e = blockIdx.x * blockDim.x + threadIdx.x;
    if (e < E) {
        int pos = atomicAdd(&cursor[de[e]], 1);
        ssrc[pos] = se[e];
    }
}

// ---------------- fused softmax-aggregate, CSR (layer 1) -------------------
template<int C>
__global__ void agg_csr_kernel(const int* __restrict__ rowptr,
                               const int* __restrict__ ssrc,
                               const float* __restrict__ als,
                               const float* __restrict__ ald,
                               const float* __restrict__ h,
                               const float* __restrict__ bias,
                               float* __restrict__ out, int n)
{
    constexpr int HC = 4 * C;
    constexpr int G  = HC / 4;
    int gt   = blockIdx.x * blockDim.x + threadIdx.x;
    int node = gt / G;
    int li   = gt % G;
    if (node >= n) return;
    int head = li / (C / 4);

    float aldv = ald[(size_t)node * 4 + head];

    float e0 = als[(size_t)node * 4 + head] + aldv;
    e0 = e0 > 0.f ? e0 : 0.2f * e0;
    float ex = __expf(e0);
    float den = ex;
    float4 hv = ((const float4*)(h + (size_t)node * HC))[li];
    float4 acc = make_float4(ex * hv.x, ex * hv.y, ex * hv.z, ex * hv.w);

    int j1 = rowptr[node + 1];
    for (int j = rowptr[node]; j < j1; j++) {
        int s = ssrc[j];
        float e = als[(size_t)s * 4 + head] + aldv;
        e = e > 0.f ? e : 0.2f * e;
        float w = __expf(e);
        den += w;
        float4 v = ((const float4*)(h + (size_t)s * HC))[li];
        acc.x = fmaf(w, v.x, acc.x);
        acc.y = fmaf(w, v.y, acc.y);
        acc.z = fmaf(w, v.z, acc.z);
        acc.w = fmaf(w, v.w, acc.w);
    }
    float inv = 1.f / den;
    float4 o;
    o.x = acc.x * inv + bias[li * 4 + 0];
    o.y = acc.y * inv + bias[li * 4 + 1];
    o.z = acc.z * inv + bias[li * 4 + 2];
    o.w = acc.w * inv + bias[li * 4 + 3];
    ((float4*)(out + (size_t)node * HC))[li] = o;
}

// ---------------- layer 2: aggregate + head-mean + bias + elu + logsoftmax -
__global__ void agg2_final_kernel(const int* __restrict__ rowptr,
                                  const int* __restrict__ ssrc,
                                  const float* __restrict__ als,
                                  const float* __restrict__ ald,
                                  const float* __restrict__ h,
                                  const float* __restrict__ b2,
                                  float* __restrict__ y, int n)
{
    int lane = threadIdx.x & 31;
    int node = (blockIdx.x * blockDim.x + threadIdx.x) >> 5;
    if (node >= n) return;
    int head = lane >> 3;

    float aldv = ald[(size_t)node * 4 + head];

    float e0 = als[(size_t)node * 4 + head] + aldv;
    e0 = e0 > 0.f ? e0 : 0.2f * e0;
    float ex = __expf(e0);
    float den = ex;
    float4 hv = ((const float4*)(h + (size_t)node * 128))[lane];
    float4 acc = make_float4(ex * hv.x, ex * hv.y, ex * hv.z, ex * hv.w);

    int j1 = rowptr[node + 1];
    for (int j = rowptr[node]; j < j1; j++) {
        int s = ssrc[j];
        float e = als[(size_t)s * 4 + head] + aldv;
        e = e > 0.f ? e : 0.2f * e;
        float w = __expf(e);
        den += w;
        float4 v = ((const float4*)(h + (size_t)s * 128))[lane];
        acc.x = fmaf(w, v.x, acc.x);
        acc.y = fmaf(w, v.y, acc.y);
        acc.z = fmaf(w, v.z, acc.z);
        acc.w = fmaf(w, v.w, acc.w);
    }
    float inv = 1.f / den;
    float4 v = make_float4(acc.x * inv, acc.y * inv, acc.z * inv, acc.w * inv);

    v.x += __shfl_xor_sync(0xffffffffu, v.x, 8);
    v.y += __shfl_xor_sync(0xffffffffu, v.y, 8);
    v.z += __shfl_xor_sync(0xffffffffu, v.z, 8);
    v.w += __shfl_xor_sync(0xffffffffu, v.w, 8);
    v.x += __shfl_xor_sync(0xffffffffu, v.x, 16);
    v.y += __shfl_xor_sync(0xffffffffu, v.y, 16);
    v.z += __shfl_xor_sync(0xffffffffu, v.z, 16);
    v.w += __shfl_xor_sync(0xffffffffu, v.w, 16);
    int c0 = (lane & 7) * 4;
    v.x = 0.25f * v.x + b2[c0 + 0];
    v.y = 0.25f * v.y + b2[c0 + 1];
    v.z = 0.25f * v.z + b2[c0 + 2];
    v.w = 0.25f * v.w + b2[c0 + 3];
    v.x = v.x > 0.f ? v.x : expm1f(v.x);
    v.y = v.y > 0.f ? v.y : expm1f(v.y);
    v.z = v.z > 0.f ? v.z : expm1f(v.z);
    v.w = v.w > 0.f ? v.w : expm1f(v.w);
    float m = fmaxf(fmaxf(v.x, v.y), fmaxf(v.z, v.w));
#pragma unroll
    for (int off = 1; off < 8; off <<= 1)
        m = fmaxf(m, __shfl_xor_sync(0xffffffffu, m, off));
    float s = expf(v.x - m) + expf(v.y - m) + expf(v.z - m) + expf(v.w - m);
#pragma unroll
    for (int off = 1; off < 8; off <<= 1)
        s += __shfl_xor_sync(0xffffffffu, s, off);
    float ls = m + logf(s);
    if (lane < 8) {
        float4 o = make_float4(v.x - ls, v.y - ls, v.z - ls, v.w - ls);
        ((float4*)(y + (size_t)node * 32))[lane] = o;
    }
}

// ---------------------------------------------------------------------------
extern "C" void kernel_launch(void* const* d_in, const int* in_sizes, int n_in,
                              void* d_out, int out_size)
{
    const float* x   = (const float*)d_in[0];
    const int*   ei  = (const int*)d_in[1];
    const float* W1  = (const float*)d_in[2];
    const float* as1 = (const float*)d_in[3];
    const float* ad1 = (const float*)d_in[4];
    const float* b1  = (const float*)d_in[5];
    const float* W2  = (const float*)d_in[6];
    const float* as2 = (const float*)d_in[7];
    const float* ad2 = (const float*)d_in[8];
    const float* b2  = (const float*)d_in[9];
    float*       y   = (float*)d_out;

    const int n = in_sizes[0] / 128;
    const int E = in_sizes[1] / 2;
    const int* se = ei;
    const int* de = ei + E;

    float *h1, *als1, *ald1, *out1, *h2, *als2, *ald2;
    int *rowptr, *cursor, *bsum, *ssrc;
    cudaGetSymbolAddress((void**)&h1,     g_h1);
    cudaGetSymbolAddress((void**)&als1,   g_als1);
    cudaGetSymbolAddress((void**)&ald1,   g_ald1);
    cudaGetSymbolAddress((void**)&out1,   g_out1);
    cudaGetSymbolAddress((void**)&h2,     g_h2);
    cudaGetSymbolAddress((void**)&als2,   g_als2);
    cudaGetSymbolAddress((void**)&ald2,   g_ald2);
    cudaGetSymbolAddress((void**)&rowptr, g_rowptr);
    cudaGetSymbolAddress((void**)&cursor, g_cursor);
    cudaGetSymbolAddress((void**)&bsum,   g_bsum);
    cudaGetSymbolAddress((void**)&ssrc,   g_ssrc);

    const int nb = (n + 2047) / 2048;

    // ---- CSR build part 1 (kernels 1-3), then gemm1 as 4th (profiled) ----
    cudaMemsetAsync(rowptr, 0, (size_t)n * sizeof(int));
    hist_kernel<<<(E + 255) / 256, 256>>>(de, E, rowptr);                  // 1
    scan_k1<<<nb, 256>>>(rowptr, n, bsum);                                 // 2
    scan_k3m<<<(n + 255) / 256, 256>>>(rowptr, n, bsum, cursor, E);        // 3

    gemm_kernel<128, 64, false>                                            // 4
        <<<dim3((n + 127) / 128, 1), 256>>>(x, W1, nullptr, as1, ad1,
                                            h1, als1, ald1, n);

    scatter_kernel<<<(E + 255) / 256, 256>>>(se, de, E, cursor, ssrc);     // 5

    // ---- layer 1 aggregation (adds b1) ----
    agg_csr_kernel<16><<<(int)(((long long)n * 16 + 255) / 256), 256>>>(
        rowptr, ssrc, als1, ald1, h1, b1, out1, n);                        // 6

    // ---- layer 2 ----
    gemm_kernel<64, 128, true>                                             // 7
        <<<dim3((n + 127) / 128, 2), 256>>>(out1, W2, b1, as2, ad2,
                                            h2, als2, ald2, n);
    agg2_final_kernel<<<(int)(((long long)n * 32 + 255) / 256), 256>>>(
        rowptr, ssrc, als2, ald2, h2, b2, y, n);                           // 8
}

// round 12
// speedup vs baseline: 1.2517x; 1.0392x over previous
#include <cuda_runtime.h>

#define MAX_N 100000
#define MAX_E 1600000

// ---------------- scratch (static __device__ arrays) ----------------------
__device__ float g_h1  [MAX_N * 64];
__device__ float g_als1[MAX_N * 4];
__device__ float g_ald1[MAX_N * 4];
__device__ float g_out1[MAX_N * 64];
__device__ float g_h2  [MAX_N * 128];
__device__ float g_als2[MAX_N * 4];
__device__ float g_ald2[MAX_N * 4];
__device__ int   g_rowptr[MAX_N + 1];
__device__ int   g_cursor[MAX_N];
__device__ int   g_bsum[128];
__device__ int   g_ssrc[MAX_E];

// ---------------- GEMM + fused attention logits (round-10 proven) ---------
// C[M,NC] = (A[M,K] (+abias)) @ W[K,NC]; tile 128x64 (blockIdx.y splits NC),
// micro 8x4, 256 threads. Epilogue computes als/ald per head.
template<int K, int NC, bool ADD_BIAS>
__global__ __launch_bounds__(256)
void gemm_kernel(const float* __restrict__ A, const float* __restrict__ W,
                 const float* __restrict__ abias,
                 const float* __restrict__ a_src, const float* __restrict__ a_dst,
                 float* __restrict__ C,
                 float* __restrict__ als, float* __restrict__ ald, int M)
{
    constexpr int KC = 32;
    __shared__ float As[128][KC + 4];
    __shared__ float Bs[KC][64];

    const int tx = threadIdx.x & 15;
    const int ty = threadIdx.x >> 4;
    const int row0 = blockIdx.x * 128;
    const int col0 = blockIdx.y * 64;

    float acc[8][4];
#pragma unroll
    for (int i = 0; i < 8; i++)
#pragma unroll
        for (int j = 0; j < 4; j++) acc[i][j] = 0.f;

    for (int kk = 0; kk < K; kk += KC) {
#pragma unroll
        for (int i = 0; i < 4; i++) {
            int idx = threadIdx.x + i * 256;
            int r = idx >> 3, c4 = idx & 7;
            float4 v = make_float4(0.f, 0.f, 0.f, 0.f);
            int gr = row0 + r;
            if (gr < M)
                v = *(const float4*)(A + (size_t)gr * K + kk + c4 * 4);
            if (ADD_BIAS) {
                v.x += abias[kk + c4 * 4 + 0];
                v.y += abias[kk + c4 * 4 + 1];
                v.z += abias[kk + c4 * 4 + 2];
                v.w += abias[kk + c4 * 4 + 3];
            }
            *(float4*)&As[r][c4 * 4] = v;
        }
#pragma unroll
        for (int i = 0; i < 2; i++) {
            int idx = threadIdx.x + i * 256;
            int r = idx >> 4, c4 = idx & 15;
            *(float4*)&Bs[r][c4 * 4] =
                *(const float4*)(W + (size_t)(kk + r) * NC + col0 + c4 * 4);
        }
        __syncthreads();

#pragma unroll
        for (int k = 0; k < KC; k++) {
            float4 b = *(float4*)&Bs[k][tx * 4];
#pragma unroll
            for (int i = 0; i < 8; i++) {
                float a = As[ty * 8 + i][k];
                acc[i][0] += a * b.x;
                acc[i][1] += a * b.y;
                acc[i][2] += a * b.z;
                acc[i][3] += a * b.w;
            }
        }
        __syncthreads();
    }

    // ---- store C ----
#pragma unroll
    for (int i = 0; i < 8; i++) {
        int gr = row0 + ty * 8 + i;
        if (gr < M)
            *(float4*)(C + (size_t)gr * NC + col0 + tx * 4) =
                make_float4(acc[i][0], acc[i][1], acc[i][2], acc[i][3]);
    }

    // ---- fused logits ----
    constexpr int CPH = NC / 4;
    constexpr int G   = CPH / 4;
    const int gcol0 = col0 + tx * 4;
    const int head = gcol0 / CPH;
    float asv[4], adv[4];
#pragma unroll
    for (int j = 0; j < 4; j++) {
        asv[j] = a_src[gcol0 + j];
        adv[j] = a_dst[gcol0 + j];
    }
#pragma unroll
    for (int i = 0; i < 8; i++) {
        float s1 = acc[i][0] * asv[0] + acc[i][1] * asv[1]
                 + acc[i][2] * asv[2] + acc[i][3] * asv[3];
        float s2 = acc[i][0] * adv[0] + acc[i][1] * adv[1]
                 + acc[i][2] * adv[2] + acc[i][3] * adv[3];
#pragma unroll
        for (int off = 1; off < G; off <<= 1) {
            s1 += __shfl_xor_sync(0xffffffffu, s1, off);
            s2 += __shfl_xor_sync(0xffffffffu, s2, off);
        }
        int gr = row0 + ty * 8 + i;
        if ((tx & (G - 1)) == 0 && gr < M) {
            als[(size_t)gr * 4 + head] = s1;
            ald[(size_t)gr * 4 + head] = s2;
        }
    }
}

// ---------------- CSR build ------------------------------------------------
__global__ void hist_kernel(const int* __restrict__ de, int E, int* __restrict__ cnt)
{
    int e = blockIdx.x * blockDim.x + threadIdx.x;
    if (e < E) atomicAdd(&cnt[de[e]], 1);
}

__global__ void scan_k1(int* __restrict__ data, int n, int* __restrict__ bsum)
{
    __shared__ int sh[256];
    int base = blockIdx.x * 2048 + threadIdx.x * 8;
    int v[8];
    int run = 0;
#pragma unroll
    for (int k = 0; k < 8; k++) {
        int t = (base + k < n) ? data[base + k] : 0;
        v[k] = run;
        run += t;
    }
    sh[threadIdx.x] = run;
    __syncthreads();
    for (int off = 1; off < 256; off <<= 1) {
        int t = (threadIdx.x >= off) ? sh[threadIdx.x - off] : 0;
        __syncthreads();
        sh[threadIdx.x] += t;
        __syncthreads();
    }
    int excl = sh[threadIdx.x] - run;
#pragma unroll
    for (int k = 0; k < 8; k++)
        if (base + k < n) data[base + k] = v[k] + excl;
    if (threadIdx.x == 255) bsum[blockIdx.x] = sh[255];
}

__global__ void scan_k3m(int* __restrict__ data, int n, const int* __restrict__ bsum,
                         int* __restrict__ cursor, int E)
{
    __shared__ int sb[128];
    __shared__ int spre;
    int blk = (blockIdx.x * 256) >> 11;
    if (threadIdx.x < 128)
        sb[threadIdx.x] = (threadIdx.x < blk) ? bsum[threadIdx.x] : 0;
    __syncthreads();
    if (threadIdx.x == 0) {
        int p = 0;
        for (int b = 0; b < blk; b++) p += sb[b];
        spre = p;
    }
    __syncthreads();
    int i = blockIdx.x * blockDim.x + threadIdx.x;
    if (i < n) {
        int v = data[i] + spre;
        data[i] = v;
        cursor[i] = v;
    }
    if (i == 0) data[n] = E;
}

__global__ void scatter_kernel(const int* __restrict__ se, const int* __restrict__ de,
                               int E, int* __restrict__ cursor, int* __restrict__ ssrc)
{
    int e = blockIdx.x * blockDim.x + threadIdx.x;
    if (e < E) {
        int pos = atomicAdd(&cursor[de[e]], 1);
        ssrc[pos] = se[e];
    }
}

// ---------------- fused softmax-aggregate, CSR (layer 1) -------------------
// half-warp per dst node, 2-edge unrolled (MLP=2), adds bias.
__global__ void agg1_kernel(const int* __restrict__ rowptr,
                            const int* __restrict__ ssrc,
                            const float* __restrict__ als,
                            const float* __restrict__ ald,
                            const float* __restrict__ h,
                            const float* __restrict__ bias,
                            float* __restrict__ out, int n)
{
    int gt   = blockIdx.x * blockDim.x + threadIdx.x;
    int node = gt >> 4;
    int li   = gt & 15;
    if (node >= n) return;
    int head = li >> 2;

    float aldv = ald[(size_t)node * 4 + head];

    float e0 = als[(size_t)node * 4 + head] + aldv;
    e0 = e0 > 0.f ? e0 : 0.2f * e0;
    float ex = __expf(e0);
    float den = ex;
    float4 hv = ((const float4*)(h + (size_t)node * 64))[li];
    float4 acc = make_float4(ex * hv.x, ex * hv.y, ex * hv.z, ex * hv.w);

    int j0 = rowptr[node], j1 = rowptr[node + 1];
    int j = j0;
    for (; j + 2 <= j1; j += 2) {
        int s0 = ssrc[j], s1 = ssrc[j + 1];
        float ea = als[(size_t)s0 * 4 + head] + aldv;
        float eb = als[(size_t)s1 * 4 + head] + aldv;
        float4 v0 = ((const float4*)(h + (size_t)s0 * 64))[li];
        float4 v1 = ((const float4*)(h + (size_t)s1 * 64))[li];
        ea = ea > 0.f ? ea : 0.2f * ea;
        eb = eb > 0.f ? eb : 0.2f * eb;
        float w0 = __expf(ea);
        float w1 = __expf(eb);
        den += w0 + w1;
        acc.x = fmaf(w0, v0.x, acc.x); acc.y = fmaf(w0, v0.y, acc.y);
        acc.z = fmaf(w0, v0.z, acc.z); acc.w = fmaf(w0, v0.w, acc.w);
        acc.x = fmaf(w1, v1.x, acc.x); acc.y = fmaf(w1, v1.y, acc.y);
        acc.z = fmaf(w1, v1.z, acc.z); acc.w = fmaf(w1, v1.w, acc.w);
    }
    if (j < j1) {
        int s = ssrc[j];
        float e = als[(size_t)s * 4 + head] + aldv;
        e = e > 0.f ? e : 0.2f * e;
        float w = __expf(e);
        den += w;
        float4 v = ((const float4*)(h + (size_t)s * 64))[li];
        acc.x = fmaf(w, v.x, acc.x);
        acc.y = fmaf(w, v.y, acc.y);
        acc.z = fmaf(w, v.z, acc.z);
        acc.w = fmaf(w, v.w, acc.w);
    }
    float inv = 1.f / den;
    float4 o;
    o.x = acc.x * inv + bias[li * 4 + 0];
    o.y = acc.y * inv + bias[li * 4 + 1];
    o.z = acc.z * inv + bias[li * 4 + 2];
    o.w = acc.w * inv + bias[li * 4 + 3];
    ((float4*)(out + (size_t)node * 64))[li] = o;
}

// ---------------- layer 2: aggregate + head-mean + bias + elu + logsoftmax -
// warp per node, 2-edge unrolled, fully fused epilogue.
__global__ void agg2_final_kernel(const int* __restrict__ rowptr,
                                  const int* __restrict__ ssrc,
                                  const float* __restrict__ als,
                                  const float* __restrict__ ald,
                                  const float* __restrict__ h,
                                  const float* __restrict__ b2,
                                  float* __restrict__ y, int n)
{
    int lane = threadIdx.x & 31;
    int node = (blockIdx.x * blockDim.x + threadIdx.x) >> 5;
    if (node >= n) return;
    int head = lane >> 3;

    float aldv = ald[(size_t)node * 4 + head];

    float e0 = als[(size_t)node * 4 + head] + aldv;
    e0 = e0 > 0.f ? e0 : 0.2f * e0;
    float ex = __expf(e0);
    float den = ex;
    float4 hv = ((const float4*)(h + (size_t)node * 128))[lane];
    float4 acc = make_float4(ex * hv.x, ex * hv.y, ex * hv.z, ex * hv.w);

    int j0 = rowptr[node], j1 = rowptr[node + 1];
    int j = j0;
    for (; j + 2 <= j1; j += 2) {
        int s0 = ssrc[j], s1 = ssrc[j + 1];
        float ea = als[(size_t)s0 * 4 + head] + aldv;
        float eb = als[(size_t)s1 * 4 + head] + aldv;
        float4 v0 = ((const float4*)(h + (size_t)s0 * 128))[lane];
        float4 v1 = ((const float4*)(h + (size_t)s1 * 128))[lane];
        ea = ea > 0.f ? ea : 0.2f * ea;
        eb = eb > 0.f ? eb : 0.2f * eb;
        float w0 = __expf(ea);
        float w1 = __expf(eb);
        den += w0 + w1;
        acc.x = fmaf(w0, v0.x, acc.x); acc.y = fmaf(w0, v0.y, acc.y);
        acc.z = fmaf(w0, v0.z, acc.z); acc.w = fmaf(w0, v0.w, acc.w);
        acc.x = fmaf(w1, v1.x, acc.x); acc.y = fmaf(w1, v1.y, acc.y);
        acc.z = fmaf(w1, v1.z, acc.z); acc.w = fmaf(w1, v1.w, acc.w);
    }
    if (j < j1) {
        int s = ssrc[j];
        float e = als[(size_t)s * 4 + head] + aldv;
        e = e > 0.f ? e : 0.2f * e;
        float w = __expf(e);
        den += w;
        float4 v = ((const float4*)(h + (size_t)s * 128))[lane];
        acc.x = fmaf(w, v.x, acc.x);
        acc.y = fmaf(w, v.y, acc.y);
        acc.z = fmaf(w, v.z, acc.z);
        acc.w = fmaf(w, v.w, acc.w);
    }
    float inv = 1.f / den;
    float4 v = make_float4(acc.x * inv, acc.y * inv, acc.z * inv, acc.w * inv);

    v.x += __shfl_xor_sync(0xffffffffu, v.x, 8);
    v.y += __shfl_xor_sync(0xffffffffu, v.y, 8);
    v.z += __shfl_xor_sync(0xffffffffu, v.z, 8);
    v.w += __shfl_xor_sync(0xffffffffu, v.w, 8);
    v.x += __shfl_xor_sync(0xffffffffu, v.x, 16);
    v.y += __shfl_xor_sync(0xffffffffu, v.y, 16);
    v.z += __shfl_xor_sync(0xffffffffu, v.z, 16);
    v.w += __shfl_xor_sync(0xffffffffu, v.w, 16);
    int c0 = (lane & 7) * 4;
    v.x = 0.25f * v.x + b2[c0 + 0];
    v.y = 0.25f * v.y + b2[c0 + 1];
    v.z = 0.25f * v.z + b2[c0 + 2];
    v.w = 0.25f * v.w + b2[c0 + 3];
    v.x = v.x > 0.f ? v.x : expm1f(v.x);
    v.y = v.y > 0.f ? v.y : expm1f(v.y);
    v.z = v.z > 0.f ? v.z : expm1f(v.z);
    v.w = v.w > 0.f ? v.w : expm1f(v.w);
    float m = fmaxf(fmaxf(v.x, v.y), fmaxf(v.z, v.w));
#pragma unroll
    for (int off = 1; off < 8; off <<= 1)
        m = fmaxf(m, __shfl_xor_sync(0xffffffffu, m, off));
    float s = expf(v.x - m) + expf(v.y - m) + expf(v.z - m) + expf(v.w - m);
#pragma unroll
    for (int off = 1; off < 8; off <<= 1)
        s += __shfl_xor_sync(0xffffffffu, s, off);
    float ls = m + logf(s);
    if (lane < 8) {
        float4 o = make_float4(v.x - ls, v.y - ls, v.z - ls, v.w - ls);
        ((float4*)(y + (size_t)node * 32))[lane] = o;
    }
}

// ---------------------------------------------------------------------------
extern "C" void kernel_launch(void* const* d_in, const int* in_sizes, int n_in,
                              void* d_out, int out_size)
{
    const float* x   = (const float*)d_in[0];
    const int*   ei  = (const int*)d_in[1];
    const float* W1  = (const float*)d_in[2];
    const float* as1 = (const float*)d_in[3];
    const float* ad1 = (const float*)d_in[4];
    const float* b1  = (const float*)d_in[5];
    const float* W2  = (const float*)d_in[6];
    const float* as2 = (const float*)d_in[7];
    const float* ad2 = (const float*)d_in[8];
    const float* b2  = (const float*)d_in[9];
    float*       y   = (float*)d_out;

    const int n = in_sizes[0] / 128;
    const int E = in_sizes[1] / 2;
    const int* se = ei;
    const int* de = ei + E;

    float *h1, *als1, *ald1, *out1, *h2, *als2, *ald2;
    int *rowptr, *cursor, *bsum, *ssrc;
    cudaGetSymbolAddress((void**)&h1,     g_h1);
    cudaGetSymbolAddress((void**)&als1,   g_als1);
    cudaGetSymbolAddress((void**)&ald1,   g_ald1);
    cudaGetSymbolAddress((void**)&out1,   g_out1);
    cudaGetSymbolAddress((void**)&h2,     g_h2);
    cudaGetSymbolAddress((void**)&als2,   g_als2);
    cudaGetSymbolAddress((void**)&ald2,   g_ald2);
    cudaGetSymbolAddress((void**)&rowptr, g_rowptr);
    cudaGetSymbolAddress((void**)&cursor, g_cursor);
    cudaGetSymbolAddress((void**)&bsum,   g_bsum);
    cudaGetSymbolAddress((void**)&ssrc,   g_ssrc);

    const int nb = (n + 2047) / 2048;

    // ---- CSR build part 1 (kernels 1-3), then gemm1 as 4th (profiled) ----
    cudaMemsetAsync(rowptr, 0, (size_t)n * sizeof(int));
    hist_kernel<<<(E + 255) / 256, 256>>>(de, E, rowptr);                  // 1
    scan_k1<<<nb, 256>>>(rowptr, n, bsum);                                 // 2
    scan_k3m<<<(n + 255) / 256, 256>>>(rowptr, n, bsum, cursor, E);        // 3

    gemm_kernel<128, 64, false>                                            // 4
        <<<dim3((n + 127) / 128, 1), 256>>>(x, W1, nullptr, as1, ad1,
                                            h1, als1, ald1, n);

    scatter_kernel<<<(E + 255) / 256, 256>>>(se, de, E, cursor, ssrc);     // 5

    // ---- layer 1 aggregation (adds b1) ----
    agg1_kernel<<<(int)(((long long)n * 16 + 255) / 256), 256>>>(
        rowptr, ssrc, als1, ald1, h1, b1, out1, n);                        // 6

    // ---- layer 2 ----
    gemm_kernel<64, 128, true>                                             // 7
        <<<dim3((n + 127) / 128, 2), 256>>>(out1, W2, b1, as2, ad2,
                                            h2, als2, ald2, n);
    agg2_final_kernel<<<(int)(((long long)n * 32 + 255) / 256), 256>>>(
        rowptr, ssrc, als2, ald2, h2, b2, y, n);                           // 8
}

// round 13
// speedup vs baseline: 1.3053x; 1.0428x over previous
#include <cuda_runtime.h>

#define MAX_N 100000
#define MAX_E 1600000

// ---------------- scratch (static __device__ arrays) ----------------------
__device__ float g_h1  [MAX_N * 64];
__device__ float g_als1[MAX_N * 4];
__device__ float g_ald1[MAX_N * 4];
__device__ float g_out1[MAX_N * 64];
__device__ float g_h2  [MAX_N * 128];
__device__ float g_als2[MAX_N * 4];
__device__ float g_ald2[MAX_N * 4];
__device__ int   g_rowptr[MAX_N + 1];
__device__ int   g_cursor[MAX_N];
__device__ int   g_bsum[128];
__device__ int   g_ssrc[MAX_E];

// ---------------- GEMM + fused attention logits (proven 47.7us) -----------
template<int K, int NC, bool ADD_BIAS>
__global__ __launch_bounds__(256)
void gemm_kernel(const float* __restrict__ A, const float* __restrict__ W,
                 const float* __restrict__ abias,
                 const float* __restrict__ a_src, const float* __restrict__ a_dst,
                 float* __restrict__ C,
                 float* __restrict__ als, float* __restrict__ ald, int M)
{
    constexpr int KC = 32;
    __shared__ float As[128][KC + 4];
    __shared__ float Bs[KC][64];

    const int tx = threadIdx.x & 15;
    const int ty = threadIdx.x >> 4;
    const int row0 = blockIdx.x * 128;
    const int col0 = blockIdx.y * 64;

    float acc[8][4];
#pragma unroll
    for (int i = 0; i < 8; i++)
#pragma unroll
        for (int j = 0; j < 4; j++) acc[i][j] = 0.f;

    for (int kk = 0; kk < K; kk += KC) {
#pragma unroll
        for (int i = 0; i < 4; i++) {
            int idx = threadIdx.x + i * 256;
            int r = idx >> 3, c4 = idx & 7;
            float4 v = make_float4(0.f, 0.f, 0.f, 0.f);
            int gr = row0 + r;
            if (gr < M)
                v = *(const float4*)(A + (size_t)gr * K + kk + c4 * 4);
            if (ADD_BIAS) {
                v.x += abias[kk + c4 * 4 + 0];
                v.y += abias[kk + c4 * 4 + 1];
                v.z += abias[kk + c4 * 4 + 2];
                v.w += abias[kk + c4 * 4 + 3];
            }
            *(float4*)&As[r][c4 * 4] = v;
        }
#pragma unroll
        for (int i = 0; i < 2; i++) {
            int idx = threadIdx.x + i * 256;
            int r = idx >> 4, c4 = idx & 15;
            *(float4*)&Bs[r][c4 * 4] =
                *(const float4*)(W + (size_t)(kk + r) * NC + col0 + c4 * 4);
        }
        __syncthreads();

#pragma unroll
        for (int k = 0; k < KC; k++) {
            float4 b = *(float4*)&Bs[k][tx * 4];
#pragma unroll
            for (int i = 0; i < 8; i++) {
                float a = As[ty * 8 + i][k];
                acc[i][0] += a * b.x;
                acc[i][1] += a * b.y;
                acc[i][2] += a * b.z;
                acc[i][3] += a * b.w;
            }
        }
        __syncthreads();
    }

    // ---- store C ----
#pragma unroll
    for (int i = 0; i < 8; i++) {
        int gr = row0 + ty * 8 + i;
        if (gr < M)
            *(float4*)(C + (size_t)gr * NC + col0 + tx * 4) =
                make_float4(acc[i][0], acc[i][1], acc[i][2], acc[i][3]);
    }

    // ---- fused logits ----
    constexpr int CPH = NC / 4;
    constexpr int G   = CPH / 4;
    const int gcol0 = col0 + tx * 4;
    const int head = gcol0 / CPH;
    float asv[4], adv[4];
#pragma unroll
    for (int j = 0; j < 4; j++) {
        asv[j] = a_src[gcol0 + j];
        adv[j] = a_dst[gcol0 + j];
    }
#pragma unroll
    for (int i = 0; i < 8; i++) {
        float s1 = acc[i][0] * asv[0] + acc[i][1] * asv[1]
                 + acc[i][2] * asv[2] + acc[i][3] * asv[3];
        float s2 = acc[i][0] * adv[0] + acc[i][1] * adv[1]
                 + acc[i][2] * adv[2] + acc[i][3] * adv[3];
#pragma unroll
        for (int off = 1; off < G; off <<= 1) {
            s1 += __shfl_xor_sync(0xffffffffu, s1, off);
            s2 += __shfl_xor_sync(0xffffffffu, s2, off);
        }
        int gr = row0 + ty * 8 + i;
        if ((tx & (G - 1)) == 0 && gr < M) {
            als[(size_t)gr * 4 + head] = s1;
            ald[(size_t)gr * 4 + head] = s2;
        }
    }
}

// ---------------- CSR build ------------------------------------------------
__global__ void hist_kernel(const int* __restrict__ de, int E, int* __restrict__ cnt)
{
    int e = blockIdx.x * blockDim.x + threadIdx.x;
    if (e < E) atomicAdd(&cnt[de[e]], 1);
}

__global__ void scan_k1(int* __restrict__ data, int n, int* __restrict__ bsum)
{
    __shared__ int sh[256];
    int base = blockIdx.x * 2048 + threadIdx.x * 8;
    int v[8];
    int run = 0;
#pragma unroll
    for (int k = 0; k < 8; k++) {
        int t = (base + k < n) ? data[base + k] : 0;
        v[k] = run;
        run += t;
    }
    sh[threadIdx.x] = run;
    __syncthreads();
    for (int off = 1; off < 256; off <<= 1) {
        int t = (threadIdx.x >= off) ? sh[threadIdx.x - off] : 0;
        __syncthreads();
        sh[threadIdx.x] += t;
        __syncthreads();
    }
    int excl = sh[threadIdx.x] - run;
#pragma unroll
    for (int k = 0; k < 8; k++)
        if (base + k < n) data[base + k] = v[k] + excl;
    if (threadIdx.x == 255) bsum[blockIdx.x] = sh[255];
}

__global__ void scan_k3m(int* __restrict__ data, int n, const int* __restrict__ bsum,
                         int* __restrict__ cursor, int E)
{
    __shared__ int sb[128];
    __shared__ int spre;
    int blk = (blockIdx.x * 256) >> 11;
    if (threadIdx.x < 128)
        sb[threadIdx.x] = (threadIdx.x < blk) ? bsum[threadIdx.x] : 0;
    __syncthreads();
    if (threadIdx.x == 0) {
        int p = 0;
        for (int b = 0; b < blk; b++) p += sb[b];
        spre = p;
    }
    __syncthreads();
    int i = blockIdx.x * blockDim.x + threadIdx.x;
    if (i < n) {
        int v = data[i] + spre;
        data[i] = v;
        cursor[i] = v;
    }
    if (i == 0) data[n] = E;
}

__global__ void scatter_kernel(const int* __restrict__ se, const int* __restrict__ de,
                               int E, int* __restrict__ cursor, int* __restrict__ ssrc)
{
    int e = blockIdx.x * blockDim.x + threadIdx.x;
    if (e < E) {
        int pos = atomicAdd(&cursor[de[e]], 1);
        ssrc[pos] = se[e];
    }
}

// ---------------- fused softmax-aggregate, CSR (layer 1) -------------------
__global__ void agg1_kernel(const int* __restrict__ rowptr,
                            const int* __restrict__ ssrc,
                            const float* __restrict__ als,
                            const float* __restrict__ ald,
                            const float* __restrict__ h,
                            const float* __restrict__ bias,
                            float* __restrict__ out, int n)
{
    int gt   = blockIdx.x * blockDim.x + threadIdx.x;
    int node = gt >> 4;
    int li   = gt & 15;
    if (node >= n) return;
    int head = li >> 2;

    float aldv = ald[(size_t)node * 4 + head];

    float e0 = als[(size_t)node * 4 + head] + aldv;
    e0 = e0 > 0.f ? e0 : 0.2f * e0;
    float ex = __expf(e0);
    float den = ex;
    float4 hv = ((const float4*)(h + (size_t)node * 64))[li];
    float4 acc = make_float4(ex * hv.x, ex * hv.y, ex * hv.z, ex * hv.w);

    int j0 = rowptr[node], j1 = rowptr[node + 1];
    int j = j0;
    for (; j + 2 <= j1; j += 2) {
        int s0 = ssrc[j], s1 = ssrc[j + 1];
        float ea = als[(size_t)s0 * 4 + head] + aldv;
        float eb = als[(size_t)s1 * 4 + head] + aldv;
        float4 v0 = ((const float4*)(h + (size_t)s0 * 64))[li];
        float4 v1 = ((const float4*)(h + (size_t)s1 * 64))[li];
        ea = ea > 0.f ? ea : 0.2f * ea;
        eb = eb > 0.f ? eb : 0.2f * eb;
        float w0 = __expf(ea);
        float w1 = __expf(eb);
        den += w0 + w1;
        acc.x = fmaf(w0, v0.x, acc.x); acc.y = fmaf(w0, v0.y, acc.y);
        acc.z = fmaf(w0, v0.z, acc.z); acc.w = fmaf(w0, v0.w, acc.w);
        acc.x = fmaf(w1, v1.x, acc.x); acc.y = fmaf(w1, v1.y, acc.y);
        acc.z = fmaf(w1, v1.z, acc.z); acc.w = fmaf(w1, v1.w, acc.w);
    }
    if (j < j1) {
        int s = ssrc[j];
        float e = als[(size_t)s * 4 + head] + aldv;
        e = e > 0.f ? e : 0.2f * e;
        float w = __expf(e);
        den += w;
        float4 v = ((const float4*)(h + (size_t)s * 64))[li];
        acc.x = fmaf(w, v.x, acc.x);
        acc.y = fmaf(w, v.y, acc.y);
        acc.z = fmaf(w, v.z, acc.z);
        acc.w = fmaf(w, v.w, acc.w);
    }
    float inv = 1.f / den;
    float4 o;
    o.x = acc.x * inv + bias[li * 4 + 0];
    o.y = acc.y * inv + bias[li * 4 + 1];
    o.z = acc.z * inv + bias[li * 4 + 2];
    o.w = acc.w * inv + bias[li * 4 + 3];
    ((float4*)(out + (size_t)node * 64))[li] = o;
}

// ---------------- layer 2: aggregate + head-mean + bias + elu + logsoftmax -
__global__ void agg2_final_kernel(const int* __restrict__ rowptr,
                                  const int* __restrict__ ssrc,
                                  const float* __restrict__ als,
                                  const float* __restrict__ ald,
                                  const float* __restrict__ h,
                                  const float* __restrict__ b2,
                                  float* __restrict__ y, int n)
{
    int lane = threadIdx.x & 31;
    int node = (blockIdx.x * blockDim.x + threadIdx.x) >> 5;
    if (node >= n) return;
    int head = lane >> 3;

    float aldv = ald[(size_t)node * 4 + head];

    float e0 = als[(size_t)node * 4 + head] + aldv;
    e0 = e0 > 0.f ? e0 : 0.2f * e0;
    float ex = __expf(e0);
    float den = ex;
    float4 hv = ((const float4*)(h + (size_t)node * 128))[lane];
    float4 acc = make_float4(ex * hv.x, ex * hv.y, ex * hv.z, ex * hv.w);

    int j0 = rowptr[node], j1 = rowptr[node + 1];
    int j = j0;
    for (; j + 2 <= j1; j += 2) {
        int s0 = ssrc[j], s1 = ssrc[j + 1];
        float ea = als[(size_t)s0 * 4 + head] + aldv;
        float eb = als[(size_t)s1 * 4 + head] + aldv;
        float4 v0 = ((const float4*)(h + (size_t)s0 * 128))[lane];
        float4 v1 = ((const float4*)(h + (size_t)s1 * 128))[lane];
        ea = ea > 0.f ? ea : 0.2f * ea;
        eb = eb > 0.f ? eb : 0.2f * eb;
        float w0 = __expf(ea);
        float w1 = __expf(eb);
        den += w0 + w1;
        acc.x = fmaf(w0, v0.x, acc.x); acc.y = fmaf(w0, v0.y, acc.y);
        acc.z = fmaf(w0, v0.z, acc.z); acc.w = fmaf(w0, v0.w, acc.w);
        acc.x = fmaf(w1, v1.x, acc.x); acc.y = fmaf(w1, v1.y, acc.y);
        acc.z = fmaf(w1, v1.z, acc.z); acc.w = fmaf(w1, v1.w, acc.w);
    }
    if (j < j1) {
        int s = ssrc[j];
        float e = als[(size_t)s * 4 + head] + aldv;
        e = e > 0.f ? e : 0.2f * e;
        float w = __expf(e);
        den += w;
        float4 v = ((const float4*)(h + (size_t)s * 128))[lane];
        acc.x = fmaf(w, v.x, acc.x);
        acc.y = fmaf(w, v.y, acc.y);
        acc.z = fmaf(w, v.z, acc.z);
        acc.w = fmaf(w, v.w, acc.w);
    }
    float inv = 1.f / den;
    float4 v = make_float4(acc.x * inv, acc.y * inv, acc.z * inv, acc.w * inv);

    v.x += __shfl_xor_sync(0xffffffffu, v.x, 8);
    v.y += __shfl_xor_sync(0xffffffffu, v.y, 8);
    v.z += __shfl_xor_sync(0xffffffffu, v.z, 8);
    v.w += __shfl_xor_sync(0xffffffffu, v.w, 8);
    v.x += __shfl_xor_sync(0xffffffffu, v.x, 16);
    v.y += __shfl_xor_sync(0xffffffffu, v.y, 16);
    v.z += __shfl_xor_sync(0xffffffffu, v.z, 16);
    v.w += __shfl_xor_sync(0xffffffffu, v.w, 16);
    int c0 = (lane & 7) * 4;
    v.x = 0.25f * v.x + b2[c0 + 0];
    v.y = 0.25f * v.y + b2[c0 + 1];
    v.z = 0.25f * v.z + b2[c0 + 2];
    v.w = 0.25f * v.w + b2[c0 + 3];
    v.x = v.x > 0.f ? v.x : expm1f(v.x);
    v.y = v.y > 0.f ? v.y : expm1f(v.y);
    v.z = v.z > 0.f ? v.z : expm1f(v.z);
    v.w = v.w > 0.f ? v.w : expm1f(v.w);
    float m = fmaxf(fmaxf(v.x, v.y), fmaxf(v.z, v.w));
#pragma unroll
    for (int off = 1; off < 8; off <<= 1)
        m = fmaxf(m, __shfl_xor_sync(0xffffffffu, m, off));
    float s = expf(v.x - m) + expf(v.y - m) + expf(v.z - m) + expf(v.w - m);
#pragma unroll
    for (int off = 1; off < 8; off <<= 1)
        s += __shfl_xor_sync(0xffffffffu, s, off);
    float ls = m + logf(s);
    if (lane < 8) {
        float4 o = make_float4(v.x - ls, v.y - ls, v.z - ls, v.w - ls);
        ((float4*)(y + (size_t)node * 32))[lane] = o;
    }
}

// ---------------------------------------------------------------------------
extern "C" void kernel_launch(void* const* d_in, const int* in_sizes, int n_in,
                              void* d_out, int out_size)
{
    const float* x   = (const float*)d_in[0];
    const int*   ei  = (const int*)d_in[1];
    const float* W1  = (const float*)d_in[2];
    const float* as1 = (const float*)d_in[3];
    const float* ad1 = (const float*)d_in[4];
    const float* b1  = (const float*)d_in[5];
    const float* W2  = (const float*)d_in[6];
    const float* as2 = (const float*)d_in[7];
    const float* ad2 = (const float*)d_in[8];
    const float* b2  = (const float*)d_in[9];
    float*       y   = (float*)d_out;

    const int n = in_sizes[0] / 128;
    const int E = in_sizes[1] / 2;
    const int* se = ei;
    const int* de = ei + E;

    float *h1, *als1, *ald1, *out1, *h2, *als2, *ald2;
    int *rowptr, *cursor, *bsum, *ssrc;
    cudaGetSymbolAddress((void**)&h1,     g_h1);
    cudaGetSymbolAddress((void**)&als1,   g_als1);
    cudaGetSymbolAddress((void**)&ald1,   g_ald1);
    cudaGetSymbolAddress((void**)&out1,   g_out1);
    cudaGetSymbolAddress((void**)&h2,     g_h2);
    cudaGetSymbolAddress((void**)&als2,   g_als2);
    cudaGetSymbolAddress((void**)&ald2,   g_ald2);
    cudaGetSymbolAddress((void**)&rowptr, g_rowptr);
    cudaGetSymbolAddress((void**)&cursor, g_cursor);
    cudaGetSymbolAddress((void**)&bsum,   g_bsum);
    cudaGetSymbolAddress((void**)&ssrc,   g_ssrc);

    // side stream + events (created once, reused across capture replays)
    static cudaStream_t s2 = nullptr;
    static cudaEvent_t evFork = nullptr, evJoin = nullptr;
    if (!s2) {
        cudaStreamCreateWithFlags(&s2, cudaStreamNonBlocking);
        cudaEventCreateWithFlags(&evFork, cudaEventDisableTiming);
        cudaEventCreateWithFlags(&evJoin, cudaEventDisableTiming);
    }

    const int nb = (n + 2047) / 2048;

    // ---- fork: CSR build on s2, concurrent with gemm1 on main ----
    cudaEventRecord(evFork, 0);
    cudaStreamWaitEvent(s2, evFork, 0);
    cudaMemsetAsync(rowptr, 0, (size_t)n * sizeof(int), s2);
    hist_kernel<<<(E + 255) / 256, 256, 0, s2>>>(de, E, rowptr);           // 1
    scan_k1<<<nb, 256, 0, s2>>>(rowptr, n, bsum);                          // 2
    scan_k3m<<<(n + 255) / 256, 256, 0, s2>>>(rowptr, n, bsum, cursor, E); // 3

    gemm_kernel<128, 64, false>                                            // 4 (main)
        <<<dim3((n + 127) / 128, 1), 256>>>(x, W1, nullptr, as1, ad1,
                                            h1, als1, ald1, n);

    scatter_kernel<<<(E + 255) / 256, 256, 0, s2>>>(se, de, E, cursor, ssrc); // 5
    cudaEventRecord(evJoin, s2);
    cudaStreamWaitEvent(0, evJoin, 0);

    // ---- layer 1 aggregation (adds b1) ----
    agg1_kernel<<<(int)(((long long)n * 16 + 255) / 256), 256>>>(
        rowptr, ssrc, als1, ald1, h1, b1, out1, n);                        // 6

    // ---- layer 2 ----
    gemm_kernel<64, 128, true>                                             // 7
        <<<dim3((n + 127) / 128, 2), 256>>>(out1, W2, b1, as2, ad2,
                                            h2, als2, ald2, n);
    agg2_final_kernel<<<(int)(((long long)n * 32 + 255) / 256), 256>>>(
        rowptr, ssrc, als2, ald2, h2, b2, y, n);                           // 8
}

// round 14
// speedup vs baseline: 1.3164x; 1.0085x over previous
#include <cuda_runtime.h>

#define MAX_N 100000
#define MAX_E 1600000

// ---------------- scratch (static __device__ arrays) ----------------------
__device__ float g_h1  [MAX_N * 64];
__device__ float g_als1[MAX_N * 4];
__device__ float g_ald1[MAX_N * 4];
__device__ float g_out1[MAX_N * 64];
__device__ float g_h2  [MAX_N * 128];
__device__ float g_als2[MAX_N * 4];
__device__ float g_ald2[MAX_N * 4];
__device__ int   g_rowptr[MAX_N + 1];
__device__ int   g_cursor[MAX_N];
__device__ int   g_bsum[128];
__device__ int   g_ssrc[MAX_E];

// ---------------- GEMM + fused attention logits (proven 48us) -------------
template<int K, int NC, bool ADD_BIAS>
__global__ __launch_bounds__(256)
void gemm_kernel(const float* __restrict__ A, const float* __restrict__ W,
                 const float* __restrict__ abias,
                 const float* __restrict__ a_src, const float* __restrict__ a_dst,
                 float* __restrict__ C,
                 float* __restrict__ als, float* __restrict__ ald, int M)
{
    constexpr int KC = 32;
    __shared__ float As[128][KC + 4];
    __shared__ float Bs[KC][64];

    const int tx = threadIdx.x & 15;
    const int ty = threadIdx.x >> 4;
    const int row0 = blockIdx.x * 128;
    const int col0 = blockIdx.y * 64;

    float acc[8][4];
#pragma unroll
    for (int i = 0; i < 8; i++)
#pragma unroll
        for (int j = 0; j < 4; j++) acc[i][j] = 0.f;

    for (int kk = 0; kk < K; kk += KC) {
#pragma unroll
        for (int i = 0; i < 4; i++) {
            int idx = threadIdx.x + i * 256;
            int r = idx >> 3, c4 = idx & 7;
            float4 v = make_float4(0.f, 0.f, 0.f, 0.f);
            int gr = row0 + r;
            if (gr < M)
                v = *(const float4*)(A + (size_t)gr * K + kk + c4 * 4);
            if (ADD_BIAS) {
                v.x += abias[kk + c4 * 4 + 0];
                v.y += abias[kk + c4 * 4 + 1];
                v.z += abias[kk + c4 * 4 + 2];
                v.w += abias[kk + c4 * 4 + 3];
            }
            *(float4*)&As[r][c4 * 4] = v;
        }
#pragma unroll
        for (int i = 0; i < 2; i++) {
            int idx = threadIdx.x + i * 256;
            int r = idx >> 4, c4 = idx & 15;
            *(float4*)&Bs[r][c4 * 4] =
                *(const float4*)(W + (size_t)(kk + r) * NC + col0 + c4 * 4);
        }
        __syncthreads();

#pragma unroll
        for (int k = 0; k < KC; k++) {
            float4 b = *(float4*)&Bs[k][tx * 4];
#pragma unroll
            for (int i = 0; i < 8; i++) {
                float a = As[ty * 8 + i][k];
                acc[i][0] += a * b.x;
                acc[i][1] += a * b.y;
                acc[i][2] += a * b.z;
                acc[i][3] += a * b.w;
            }
        }
        __syncthreads();
    }

    // ---- store C ----
#pragma unroll
    for (int i = 0; i < 8; i++) {
        int gr = row0 + ty * 8 + i;
        if (gr < M)
            *(float4*)(C + (size_t)gr * NC + col0 + tx * 4) =
                make_float4(acc[i][0], acc[i][1], acc[i][2], acc[i][3]);
    }

    // ---- fused logits ----
    constexpr int CPH = NC / 4;
    constexpr int G   = CPH / 4;
    const int gcol0 = col0 + tx * 4;
    const int head = gcol0 / CPH;
    float asv[4], adv[4];
#pragma unroll
    for (int j = 0; j < 4; j++) {
        asv[j] = a_src[gcol0 + j];
        adv[j] = a_dst[gcol0 + j];
    }
#pragma unroll
    for (int i = 0; i < 8; i++) {
        float s1 = acc[i][0] * asv[0] + acc[i][1] * asv[1]
                 + acc[i][2] * asv[2] + acc[i][3] * asv[3];
        float s2 = acc[i][0] * adv[0] + acc[i][1] * adv[1]
                 + acc[i][2] * adv[2] + acc[i][3] * adv[3];
#pragma unroll
        for (int off = 1; off < G; off <<= 1) {
            s1 += __shfl_xor_sync(0xffffffffu, s1, off);
            s2 += __shfl_xor_sync(0xffffffffu, s2, off);
        }
        int gr = row0 + ty * 8 + i;
        if ((tx & (G - 1)) == 0 && gr < M) {
            als[(size_t)gr * 4 + head] = s1;
            ald[(size_t)gr * 4 + head] = s2;
        }
    }
}

// ---------------- CSR build ------------------------------------------------
__global__ void hist_kernel(const int* __restrict__ de, int E, int* __restrict__ cnt)
{
    int e = blockIdx.x * blockDim.x + threadIdx.x;
    if (e < E) atomicAdd(&cnt[de[e]], 1);
}

__global__ void scan_k1(int* __restrict__ data, int n, int* __restrict__ bsum)
{
    __shared__ int sh[256];
    int base = blockIdx.x * 2048 + threadIdx.x * 8;
    int v[8];
    int run = 0;
#pragma unroll
    for (int k = 0; k < 8; k++) {
        int t = (base + k < n) ? data[base + k] : 0;
        v[k] = run;
        run += t;
    }
    sh[threadIdx.x] = run;
    __syncthreads();
    for (int off = 1; off < 256; off <<= 1) {
        int t = (threadIdx.x >= off) ? sh[threadIdx.x - off] : 0;
        __syncthreads();
        sh[threadIdx.x] += t;
        __syncthreads();
    }
    int excl = sh[threadIdx.x] - run;
#pragma unroll
    for (int k = 0; k < 8; k++)
        if (base + k < n) data[base + k] = v[k] + excl;
    if (threadIdx.x == 255) bsum[blockIdx.x] = sh[255];
}

__global__ void scan_k3m(int* __restrict__ data, int n, const int* __restrict__ bsum,
                         int* __restrict__ cursor, int E)
{
    __shared__ int sb[128];
    __shared__ int spre;
    int blk = (blockIdx.x * 256) >> 11;
    if (threadIdx.x < 128)
        sb[threadIdx.x] = (threadIdx.x < blk) ? bsum[threadIdx.x] : 0;
    __syncthreads();
    if (threadIdx.x == 0) {
        int p = 0;
        for (int b = 0; b < blk; b++) p += sb[b];
        spre = p;
    }
    __syncthreads();
    int i = blockIdx.x * blockDim.x + threadIdx.x;
    if (i < n) {
        int v = data[i] + spre;
        data[i] = v;
        cursor[i] = v;
    }
    if (i == 0) data[n] = E;
}

__global__ void scatter_kernel(const int* __restrict__ se, const int* __restrict__ de,
                               int E, int* __restrict__ cursor, int* __restrict__ ssrc)
{
    int e = blockIdx.x * blockDim.x + threadIdx.x;
    if (e < E) {
        int pos = atomicAdd(&cursor[de[e]], 1);
        ssrc[pos] = se[e];
    }
}

// ---------------- fused softmax-aggregate, CSR (layer 1) -------------------
// half-warp per dst node, 4-edge unrolled (MLP=4), adds bias.
__global__ void agg1_kernel(const int* __restrict__ rowptr,
                            const int* __restrict__ ssrc,
                            const float* __restrict__ als,
                            const float* __restrict__ ald,
                            const float* __restrict__ h,
                            const float* __restrict__ bias,
                            float* __restrict__ out, int n)
{
    int gt   = blockIdx.x * blockDim.x + threadIdx.x;
    int node = gt >> 4;
    int li   = gt & 15;
    if (node >= n) return;
    int head = li >> 2;

    float aldv = ald[(size_t)node * 4 + head];

    float e0 = als[(size_t)node * 4 + head] + aldv;
    e0 = e0 > 0.f ? e0 : 0.2f * e0;
    float ex = __expf(e0);
    float den = ex;
    float4 hv = ((const float4*)(h + (size_t)node * 64))[li];
    float4 acc = make_float4(ex * hv.x, ex * hv.y, ex * hv.z, ex * hv.w);

    int j0 = rowptr[node], j1 = rowptr[node + 1];
    int j = j0;
    for (; j + 4 <= j1; j += 4) {
        int s0 = ssrc[j], s1 = ssrc[j + 1], s2 = ssrc[j + 2], s3 = ssrc[j + 3];
        float ea = als[(size_t)s0 * 4 + head];
        float eb = als[(size_t)s1 * 4 + head];
        float ec = als[(size_t)s2 * 4 + head];
        float ed = als[(size_t)s3 * 4 + head];
        float4 v0 = ((const float4*)(h + (size_t)s0 * 64))[li];
        float4 v1 = ((const float4*)(h + (size_t)s1 * 64))[li];
        float4 v2 = ((const float4*)(h + (size_t)s2 * 64))[li];
        float4 v3 = ((const float4*)(h + (size_t)s3 * 64))[li];
        ea += aldv; eb += aldv; ec += aldv; ed += aldv;
        ea = ea > 0.f ? ea : 0.2f * ea;
        eb = eb > 0.f ? eb : 0.2f * eb;
        ec = ec > 0.f ? ec : 0.2f * ec;
        ed = ed > 0.f ? ed : 0.2f * ed;
        float w0 = __expf(ea), w1 = __expf(eb), w2 = __expf(ec), w3 = __expf(ed);
        den += (w0 + w1) + (w2 + w3);
        acc.x = fmaf(w0, v0.x, acc.x); acc.y = fmaf(w0, v0.y, acc.y);
        acc.z = fmaf(w0, v0.z, acc.z); acc.w = fmaf(w0, v0.w, acc.w);
        acc.x = fmaf(w1, v1.x, acc.x); acc.y = fmaf(w1, v1.y, acc.y);
        acc.z = fmaf(w1, v1.z, acc.z); acc.w = fmaf(w1, v1.w, acc.w);
        acc.x = fmaf(w2, v2.x, acc.x); acc.y = fmaf(w2, v2.y, acc.y);
        acc.z = fmaf(w2, v2.z, acc.z); acc.w = fmaf(w2, v2.w, acc.w);
        acc.x = fmaf(w3, v3.x, acc.x); acc.y = fmaf(w3, v3.y, acc.y);
        acc.z = fmaf(w3, v3.z, acc.z); acc.w = fmaf(w3, v3.w, acc.w);
    }
    for (; j < j1; j++) {
        int s = ssrc[j];
        float e = als[(size_t)s * 4 + head] + aldv;
        e = e > 0.f ? e : 0.2f * e;
        float w = __expf(e);
        den += w;
        float4 v = ((const float4*)(h + (size_t)s * 64))[li];
        acc.x = fmaf(w, v.x, acc.x);
        acc.y = fmaf(w, v.y, acc.y);
        acc.z = fmaf(w, v.z, acc.z);
        acc.w = fmaf(w, v.w, acc.w);
    }
    float inv = 1.f / den;
    float4 o;
    o.x = acc.x * inv + bias[li * 4 + 0];
    o.y = acc.y * inv + bias[li * 4 + 1];
    o.z = acc.z * inv + bias[li * 4 + 2];
    o.w = acc.w * inv + bias[li * 4 + 3];
    ((float4*)(out + (size_t)node * 64))[li] = o;
}

// ---------------- layer 2: aggregate + head-mean + bias + elu + logsoftmax -
// warp per node, 4-edge unrolled, fully fused epilogue.
__global__ void agg2_final_kernel(const int* __restrict__ rowptr,
                                  const int* __restrict__ ssrc,
                                  const float* __restrict__ als,
                                  const float* __restrict__ ald,
                                  const float* __restrict__ h,
                                  const float* __restrict__ b2,
                                  float* __restrict__ y, int n)
{
    int lane = threadIdx.x & 31;
    int node = (blockIdx.x * blockDim.x + threadIdx.x) >> 5;
    if (node >= n) return;
    int head = lane >> 3;

    float aldv = ald[(size_t)node * 4 + head];

    float e0 = als[(size_t)node * 4 + head] + aldv;
    e0 = e0 > 0.f ? e0 : 0.2f * e0;
    float ex = __expf(e0);
    float den = ex;
    float4 hv = ((const float4*)(h + (size_t)node * 128))[lane];
    float4 acc = make_float4(ex * hv.x, ex * hv.y, ex * hv.z, ex * hv.w);

    int j0 = rowptr[node], j1 = rowptr[node + 1];
    int j = j0;
    for (; j + 4 <= j1; j += 4) {
        int s0 = ssrc[j], s1 = ssrc[j + 1], s2 = ssrc[j + 2], s3 = ssrc[j + 3];
        float ea = als[(size_t)s0 * 4 + head];
        float eb = als[(size_t)s1 * 4 + head];
        float ec = als[(size_t)s2 * 4 + head];
        float ed = als[(size_t)s3 * 4 + head];
        float4 v0 = ((const float4*)(h + (size_t)s0 * 128))[lane];
        float4 v1 = ((const float4*)(h + (size_t)s1 * 128))[lane];
        float4 v2 = ((const float4*)(h + (size_t)s2 * 128))[lane];
        float4 v3 = ((const float4*)(h + (size_t)s3 * 128))[lane];
        ea += aldv; eb += aldv; ec += aldv; ed += aldv;
        ea = ea > 0.f ? ea : 0.2f * ea;
        eb = eb > 0.f ? eb : 0.2f * eb;
        ec = ec > 0.f ? ec : 0.2f * ec;
        ed = ed > 0.f ? ed : 0.2f * ed;
        float w0 = __expf(ea), w1 = __expf(eb), w2 = __expf(ec), w3 = __expf(ed);
        den += (w0 + w1) + (w2 + w3);
        acc.x = fmaf(w0, v0.x, acc.x); acc.y = fmaf(w0, v0.y, acc.y);
        acc.z = fmaf(w0, v0.z, acc.z); acc.w = fmaf(w0, v0.w, acc.w);
        acc.x = fmaf(w1, v1.x, acc.x); acc.y = fmaf(w1, v1.y, acc.y);
        acc.z = fmaf(w1, v1.z, acc.z); acc.w = fmaf(w1, v1.w, acc.w);
        acc.x = fmaf(w2, v2.x, acc.x); acc.y = fmaf(w2, v2.y, acc.y);
        acc.z = fmaf(w2, v2.z, acc.z); acc.w = fmaf(w2, v2.w, acc.w);
        acc.x = fmaf(w3, v3.x, acc.x); acc.y = fmaf(w3, v3.y, acc.y);
        acc.z = fmaf(w3, v3.z, acc.z); acc.w = fmaf(w3, v3.w, acc.w);
    }
    for (; j < j1; j++) {
        int s = ssrc[j];
        float e = als[(size_t)s * 4 + head] + aldv;
        e = e > 0.f ? e : 0.2f * e;
        float w = __expf(e);
        den += w;
        float4 v = ((const float4*)(h + (size_t)s * 128))[lane];
        acc.x = fmaf(w, v.x, acc.x);
        acc.y = fmaf(w, v.y, acc.y);
        acc.z = fmaf(w, v.z, acc.z);
        acc.w = fmaf(w, v.w, acc.w);
    }
    float inv = 1.f / den;
    float4 v = make_float4(acc.x * inv, acc.y * inv, acc.z * inv, acc.w * inv);

    v.x += __shfl_xor_sync(0xffffffffu, v.x, 8);
    v.y += __shfl_xor_sync(0xffffffffu, v.y, 8);
    v.z += __shfl_xor_sync(0xffffffffu, v.z, 8);
    v.w += __shfl_xor_sync(0xffffffffu, v.w, 8);
    v.x += __shfl_xor_sync(0xffffffffu, v.x, 16);
    v.y += __shfl_xor_sync(0xffffffffu, v.y, 16);
    v.z += __shfl_xor_sync(0xffffffffu, v.z, 16);
    v.w += __shfl_xor_sync(0xffffffffu, v.w, 16);
    int c0 = (lane & 7) * 4;
    v.x = 0.25f * v.x + b2[c0 + 0];
    v.y = 0.25f * v.y + b2[c0 + 1];
    v.z = 0.25f * v.z + b2[c0 + 2];
    v.w = 0.25f * v.w + b2[c0 + 3];
    v.x = v.x > 0.f ? v.x : expm1f(v.x);
    v.y = v.y > 0.f ? v.y : expm1f(v.y);
    v.z = v.z > 0.f ? v.z : expm1f(v.z);
    v.w = v.w > 0.f ? v.w : expm1f(v.w);
    float m = fmaxf(fmaxf(v.x, v.y), fmaxf(v.z, v.w));
#pragma unroll
    for (int off = 1; off < 8; off <<= 1)
        m = fmaxf(m, __shfl_xor_sync(0xffffffffu, m, off));
    float s = expf(v.x - m) + expf(v.y - m) + expf(v.z - m) + expf(v.w - m);
#pragma unroll
    for (int off = 1; off < 8; off <<= 1)
        s += __shfl_xor_sync(0xffffffffu, s, off);
    float ls = m + logf(s);
    if (lane < 8) {
        float4 o = make_float4(v.x - ls, v.y - ls, v.z - ls, v.w - ls);
        ((float4*)(y + (size_t)node * 32))[lane] = o;
    }
}

// ---------------------------------------------------------------------------
extern "C" void kernel_launch(void* const* d_in, const int* in_sizes, int n_in,
                              void* d_out, int out_size)
{
    const float* x   = (const float*)d_in[0];
    const int*   ei  = (const int*)d_in[1];
    const float* W1  = (const float*)d_in[2];
    const float* as1 = (const float*)d_in[3];
    const float* ad1 = (const float*)d_in[4];
    const float* b1  = (const float*)d_in[5];
    const float* W2  = (const float*)d_in[6];
    const float* as2 = (const float*)d_in[7];
    const float* ad2 = (const float*)d_in[8];
    const float* b2  = (const float*)d_in[9];
    float*       y   = (float*)d_out;

    const int n = in_sizes[0] / 128;
    const int E = in_sizes[1] / 2;
    const int* se = ei;
    const int* de = ei + E;

    float *h1, *als1, *ald1, *out1, *h2, *als2, *ald2;
    int *rowptr, *cursor, *bsum, *ssrc;
    cudaGetSymbolAddress((void**)&h1,     g_h1);
    cudaGetSymbolAddress((void**)&als1,   g_als1);
    cudaGetSymbolAddress((void**)&ald1,   g_ald1);
    cudaGetSymbolAddress((void**)&out1,   g_out1);
    cudaGetSymbolAddress((void**)&h2,     g_h2);
    cudaGetSymbolAddress((void**)&als2,   g_als2);
    cudaGetSymbolAddress((void**)&ald2,   g_ald2);
    cudaGetSymbolAddress((void**)&rowptr, g_rowptr);
    cudaGetSymbolAddress((void**)&cursor, g_cursor);
    cudaGetSymbolAddress((void**)&bsum,   g_bsum);
    cudaGetSymbolAddress((void**)&ssrc,   g_ssrc);

    // side stream + events (created once, reused across capture replays)
    static cudaStream_t s2 = nullptr;
    static cudaEvent_t evFork = nullptr, evJoin = nullptr;
    if (!s2) {
        cudaStreamCreateWithFlags(&s2, cudaStreamNonBlocking);
        cudaEventCreateWithFlags(&evFork, cudaEventDisableTiming);
        cudaEventCreateWithFlags(&evJoin, cudaEventDisableTiming);
    }

    const int nb = (n + 2047) / 2048;

    // ---- fork: CSR build on s2, concurrent with gemm1 on main ----
    cudaEventRecord(evFork, 0);
    cudaStreamWaitEvent(s2, evFork, 0);
    cudaMemsetAsync(rowptr, 0, (size_t)n * sizeof(int), s2);
    hist_kernel<<<(E + 255) / 256, 256, 0, s2>>>(de, E, rowptr);           // 1
    scan_k1<<<nb, 256, 0, s2>>>(rowptr, n, bsum);                          // 2
    scan_k3m<<<(n + 255) / 256, 256, 0, s2>>>(rowptr, n, bsum, cursor, E); // 3

    gemm_kernel<128, 64, false>                                            // 4 (main)
        <<<dim3((n + 127) / 128, 1), 256>>>(x, W1, nullptr, as1, ad1,
                                            h1, als1, ald1, n);

    scatter_kernel<<<(E + 255) / 256, 256, 0, s2>>>(se, de, E, cursor, ssrc); // 5
    cudaEventRecord(evJoin, s2);
    cudaStreamWaitEvent(0, evJoin, 0);

    // ---- layer 1 aggregation (adds b1) ----
    agg1_kernel<<<(int)(((long long)n * 16 + 255) / 256), 256>>>(
        rowptr, ssrc, als1, ald1, h1, b1, out1, n);                        // 6

    // ---- layer 2 ----
    gemm_kernel<64, 128, true>                                             // 7
        <<<dim3((n + 127) / 128, 2), 256>>>(out1, W2, b1, as2, ad2,
                                            h2, als2, ald2, n);
    agg2_final_kernel<<<(int)(((long long)n * 32 + 255) / 256), 256>>>(
        rowptr, ssrc, als2, ald2, h2, b2, y, n);                           // 8
}